// round 13
// baseline (speedup 1.0000x reference)
#include <cuda_runtime.h>
#include <cuda_fp16.h>
#include <math.h>
#include <stdint.h>

// Problem dims
#define B_  2
#define T_  2048
#define E_  1024
#define H_  16
#define D_  64
#define MROWS (B_*T_)            // 4096
#define QKVN  (3*E_)             // 3072
#define MEXP  4099               // 4E+3
// padded K dims for tensor-core GEMMs (multiples of 64)
#define KP1   1088               // pads 1025 and 1040
#define KP4   4160               // pads 4100
#define NP_ME 4224               // padded N for mlp expand (4099 -> 33*128)

// ---------------- scratch (static device globals; no allocation) -------------
__device__ __half g_l1 [MROWS*KP1];
__device__ __half g_qkv[MROWS*QKVN];
__device__ __half g_Q  [B_*H_*T_*D_];
__device__ __half g_Kr [B_*H_*T_*D_];
__device__ __half g_V  [B_*H_*T_*D_];
__device__ float  g_qt [B_*H_*T_];
__device__ float  g_kt [B_*H_*T_];
__device__ float  g_v0 [B_*H_*T_];
__device__ __half g_o  [MROWS*KP1];
__device__ float  g_y1 [MROWS*E_];
__device__ __half g_l2 [MROWS*KP1];
__device__ __half g_hp [MROWS*KP4];
// transposed + fp16-rounded + zero-padded weights: Wt[N,K]
__device__ __half g_wt_qkv[QKVN*KP1];
__device__ __half g_wt_ap [E_*KP1];
__device__ __half g_wt_me [NP_ME*KP1];
__device__ __half g_wt_ms [E_*KP4];

// ---------------- helpers -----------------------------------------------------
__device__ __forceinline__ uint32_t smem_u32(const void* p) {
    uint32_t a;
    asm("{ .reg .u64 t; cvta.to.shared.u64 t, %1; cvt.u32.u64 %0, t; }" : "=r"(a) : "l"(p));
    return a;
}
#define CP_ASYNC16(dst, src) \
    asm volatile("cp.async.cg.shared.global [%0], [%1], 16;" :: "r"(dst), "l"(src))
#define CP_COMMIT()  asm volatile("cp.async.commit_group;")
#define CP_WAIT(n)   asm volatile("cp.async.wait_group %0;" :: "n"(n))

// fp16 mma, fp32 accumulate
__device__ __forceinline__ void mma_f16(float* c, const uint32_t* a, const uint32_t* b) {
    asm volatile(
        "mma.sync.aligned.m16n8k16.row.col.f32.f16.f16.f32 "
        "{%0,%1,%2,%3}, {%4,%5,%6,%7}, {%8,%9}, {%0,%1,%2,%3};"
        : "+f"(c[0]), "+f"(c[1]), "+f"(c[2]), "+f"(c[3])
        : "r"(a[0]), "r"(a[1]), "r"(a[2]), "r"(a[3]), "r"(b[0]), "r"(b[1]));
}
__device__ __forceinline__ void ldsm_x4(uint32_t& r0, uint32_t& r1,
                                        uint32_t& r2, uint32_t& r3, uint32_t addr) {
    asm volatile("ldmatrix.sync.aligned.m8n8.x4.shared.b16 {%0,%1,%2,%3}, [%4];"
        : "=r"(r0), "=r"(r1), "=r"(r2), "=r"(r3) : "r"(addr));
}
__device__ __forceinline__ void ldsm_x4_t(uint32_t& r0, uint32_t& r1,
                                          uint32_t& r2, uint32_t& r3, uint32_t addr) {
    asm volatile("ldmatrix.sync.aligned.m8n8.x4.trans.shared.b16 {%0,%1,%2,%3}, [%4];"
        : "=r"(r0), "=r"(r1), "=r"(r2), "=r"(r3) : "r"(addr));
}

__device__ __forceinline__ float block_reduce_sum(float v, float* red) {
    int tid = threadIdx.x;
    #pragma unroll
    for (int o = 16; o; o >>= 1) v += __shfl_xor_sync(0xffffffffu, v, o);
    if ((tid & 31) == 0) red[tid >> 5] = v;
    __syncthreads();
    float r = (tid < (int)(blockDim.x >> 5)) ? red[tid] : 0.f;
    if (tid < 32) {
        #pragma unroll
        for (int o = 16; o; o >>= 1) r += __shfl_xor_sync(0xffffffffu, r, o);
        if (tid == 0) red[0] = r;
    }
    __syncthreads();
    float out = red[0];
    __syncthreads();
    return out;
}

// ---------------- merged weight transpose + fp16 round + zero pad ------------
#define TC0 (34*96)     // qkv : K=1025 N=3072 Kpad=KP1
#define TC1 (34*32)     // ap  : K=1040 N=1024 Kpad=KP1
#define TC2 (34*132)    // me  : K=1025 N=4099 Kpad=KP1, Npad=4224
#define TC3 (130*32)    // ms  : K=4100 N=1024 Kpad=KP4
__global__ void transpose_all_kernel(const float* __restrict__ w_qkv,
                                     const float* __restrict__ w_ap,
                                     const float* __restrict__ w_me,
                                     const float* __restrict__ w_ms) {
    __shared__ float s[32][33];
    int id = blockIdx.x;
    const float* W; __half* Wt;
    int K, N, Kpad, nx, r;
    if (id < TC0)                  { r = id;                W = w_qkv; Wt = g_wt_qkv; K = 1025; N = 3072; Kpad = KP1; nx = 34; }
    else if (id < TC0+TC1)         { r = id - TC0;          W = w_ap;  Wt = g_wt_ap;  K = 1040; N = 1024; Kpad = KP1; nx = 34; }
    else if (id < TC0+TC1+TC2)     { r = id - TC0 - TC1;    W = w_me;  Wt = g_wt_me;  K = 1025; N = 4099; Kpad = KP1; nx = 34; }
    else                           { r = id - TC0 - TC1-TC2;W = w_ms;  Wt = g_wt_ms;  K = 4100; N = 1024; Kpad = KP4; nx = 130; }
    int k0 = (r % nx) * 32, n0 = (r / nx) * 32;
    int tx = threadIdx.x, ty = threadIdx.y;          // 32 x 8
    #pragma unroll
    for (int yy = ty; yy < 32; yy += 8) {
        int k = k0 + yy, n = n0 + tx;
        float v = (k < K && n < N) ? W[(size_t)k * N + n] : 0.f;
        s[yy][tx] = v;
    }
    __syncthreads();
    #pragma unroll
    for (int yy = ty; yy < 32; yy += 8) {
        int n = n0 + yy, k = k0 + tx;
        Wt[(size_t)n * Kpad + k] = __float2half_rn(s[tx][yy]);
    }
}

// ---------------- fp16 tensor-core GEMM (mma.sync m16n8k16 + ldmatrix) --------
// BK=64 chunks. modes:
//  1: C(half)[r*ldc + 1 + c] = fp16(gelu(acc + bias))
//  2: C(half)[r*ldc + c]     = fp16(acc + bias)
//  3: C(float)[r*ldc + c]    = acc + bias + X2[r*E_ + c]          (resid fuse)
//  4: C(float)[r*ldc + c]    = acc + bias + X2[r*E_ + c]          (C=out+1, ldc=1025)
#define HSTR 72                      // halves per SMEM row (144 B) — conflict-free
#define HBUF (128*HSTR)              // halves per buffer
#define HBYTES (HBUF*2)              // bytes per buffer (18432)
__global__ void __launch_bounds__(256, 2) gemm_f16_kernel(
        const __half* __restrict__ A, int lda,
        const __half* __restrict__ Bt, int ldb,
        const float* __restrict__ bias,
        void* __restrict__ Cv, int ldc, int Nact, int nchunks, int mode,
        const float* __restrict__ X2) {
    extern __shared__ __half hsm[];
    uint32_t smaddr = smem_u32(hsm);
    int tid = threadIdx.x;
    int lane = tid & 31, w = tid >> 5;
    int grp = lane >> 2, tig = lane & 3;
    int wm = w >> 1, wn = w & 1;
    int row0 = blockIdx.y * 128, col0 = blockIdx.x * 128;

    int q8 = lane >> 3, rr = lane & 7;
    uint32_t aoffA[2], aoffB[4];
    #pragma unroll
    for (int mi = 0; mi < 2; ++mi) {
        int rowa = wm * 32 + mi * 16 + (q8 & 1) * 8 + rr;
        aoffA[mi] = smaddr + (uint32_t)rowa * (HSTR * 2) + (q8 >> 1) * 16;
    }
    #pragma unroll
    for (int j = 0; j < 4; ++j) {
        int nb = wn * 64 + j * 16 + (q8 >> 1) * 8 + rr;
        aoffB[j] = smaddr + 2 * HBYTES + (uint32_t)nb * (HSTR * 2) + (q8 & 1) * 16;
    }

    float acc[2][8][4];
    #pragma unroll
    for (int mi = 0; mi < 2; ++mi)
        #pragma unroll
        for (int ni = 0; ni < 8; ++ni)
            #pragma unroll
            for (int cc = 0; cc < 4; ++cc) acc[mi][ni][cc] = 0.f;

    const __half* Arow = A  + (size_t)row0 * lda;
    const __half* Brow = Bt + (size_t)col0 * ldb;

    auto load_chunk = [&](int buf, int kc) {
        int k0 = kc * 64;
        uint32_t abase = smaddr + buf * HBYTES;
        uint32_t bbase = smaddr + 2 * HBYTES + buf * HBYTES;
        #pragma unroll
        for (int u = 0; u < 4; ++u) {
            int idx = tid + u * 256;             // 0..1023
            int r = idx >> 3, c = idx & 7;       // 128 rows x 8 16B-chunks
            CP_ASYNC16(abase + r * (HSTR * 2) + c * 16,
                       Arow + (size_t)r * lda + k0 + c * 8);
            CP_ASYNC16(bbase + r * (HSTR * 2) + c * 16,
                       Brow + (size_t)r * ldb + k0 + c * 8);
        }
        CP_COMMIT();
    };

    load_chunk(0, 0);
    for (int i = 0; i < nchunks; ++i) {
        int buf = i & 1;
        if (i + 1 < nchunks) { load_chunk(buf ^ 1, i + 1); CP_WAIT(1); }
        else                 { CP_WAIT(0); }
        __syncthreads();
        uint32_t bufofs = buf * HBYTES;
        #pragma unroll
        for (int ks = 0; ks < 4; ++ks) {         // four k16 steps per 64-chunk
            uint32_t kofs = bufofs + ks * 32;
            uint32_t a[2][4];
            ldsm_x4(a[0][0], a[0][1], a[0][2], a[0][3], aoffA[0] + kofs);
            ldsm_x4(a[1][0], a[1][1], a[1][2], a[1][3], aoffA[1] + kofs);
            uint32_t b[8][2];
            #pragma unroll
            for (int j = 0; j < 4; ++j) {
                uint32_t r0, r1, r2, r3;
                ldsm_x4(r0, r1, r2, r3, aoffB[j] + kofs);
                b[2*j][0] = r0;   b[2*j][1] = r1;
                b[2*j+1][0] = r2; b[2*j+1][1] = r3;
            }
            #pragma unroll
            for (int mi = 0; mi < 2; ++mi)
                #pragma unroll
                for (int ni = 0; ni < 8; ++ni)
                    mma_f16(acc[mi][ni], a[mi], b[ni]);
        }
        __syncthreads();
    }

    if (mode == 2) {
        __half* C = (__half*)Cv;
        #pragma unroll
        for (int mi = 0; mi < 2; ++mi) {
            int rbase = row0 + wm * 32 + mi * 16 + grp;
            #pragma unroll
            for (int ni = 0; ni < 8; ++ni) {
                int gc = col0 + wn * 64 + ni * 8 + tig * 2;
                if (gc < Nact) {
                    float b0 = bias ? bias[gc] : 0.f;
                    float b1 = (bias && gc + 1 < Nact) ? bias[gc + 1] : 0.f;
                    __half* p0 = C + (size_t)rbase * ldc + gc;
                    __half* p1 = C + (size_t)(rbase + 8) * ldc + gc;
                    p0[0] = __float2half_rn(acc[mi][ni][0] + b0);
                    if (gc + 1 < Nact) p0[1] = __float2half_rn(acc[mi][ni][1] + b1);
                    p1[0] = __float2half_rn(acc[mi][ni][2] + b0);
                    if (gc + 1 < Nact) p1[1] = __float2half_rn(acc[mi][ni][3] + b1);
                }
            }
        }
    } else if (mode == 1) {
        __half* C = (__half*)Cv;
        #pragma unroll
        for (int mi = 0; mi < 2; ++mi) {
            int rbase = row0 + wm * 32 + mi * 16 + grp;
            #pragma unroll
            for (int ni = 0; ni < 8; ++ni) {
                int gc = col0 + wn * 64 + ni * 8 + tig * 2;
                if (gc < Nact) {
                    float b0 = bias ? bias[gc] : 0.f;
                    float b1 = (bias && gc + 1 < Nact) ? bias[gc + 1] : 0.f;
                    float v0 = acc[mi][ni][0] + b0;
                    float v1 = acc[mi][ni][1] + b1;
                    float v2 = acc[mi][ni][2] + b0;
                    float v3 = acc[mi][ni][3] + b1;
                    float g0 = 0.5f * v0 * (1.0f + erff(v0 * 0.70710678118654752f));
                    float g1 = 0.5f * v1 * (1.0f + erff(v1 * 0.70710678118654752f));
                    float g2 = 0.5f * v2 * (1.0f + erff(v2 * 0.70710678118654752f));
                    float g3 = 0.5f * v3 * (1.0f + erff(v3 * 0.70710678118654752f));
                    __half* p0 = C + (size_t)rbase * ldc + 1 + gc;
                    __half* p1 = C + (size_t)(rbase + 8) * ldc + 1 + gc;
                    p0[0] = __float2half_rn(g0);
                    if (gc + 1 < Nact) p0[1] = __float2half_rn(g1);
                    p1[0] = __float2half_rn(g2);
                    if (gc + 1 < Nact) p1[1] = __float2half_rn(g3);
                }
            }
        }
    } else {   // modes 3/4: fp32 out with fused residual add (X2 stride E_)
        float* C = (float*)Cv;
        #pragma unroll
        for (int mi = 0; mi < 2; ++mi) {
            int rbase = row0 + wm * 32 + mi * 16 + grp;
            #pragma unroll
            for (int ni = 0; ni < 8; ++ni) {
                int gc = col0 + wn * 64 + ni * 8 + tig * 2;
                if (gc < Nact) {
                    float b0 = bias ? bias[gc] : 0.f;
                    float b1 = (bias && gc + 1 < Nact) ? bias[gc + 1] : 0.f;
                    const float* x0 = X2 + (size_t)rbase * E_ + gc;
                    const float* x1 = X2 + (size_t)(rbase + 8) * E_ + gc;
                    float* p0 = C + (size_t)rbase * ldc + gc;
                    float* p1 = C + (size_t)(rbase + 8) * ldc + gc;
                    p0[0] = acc[mi][ni][0] + b0 + x0[0];
                    if (gc + 1 < Nact) p0[1] = acc[mi][ni][1] + b1 + x0[1];
                    p1[0] = acc[mi][ni][2] + b0 + x1[0];
                    if (gc + 1 < Nact) p1[1] = acc[mi][ni][3] + b1 + x1[1];
                }
            }
        }
    }
}

// ---------------- kernel 1: LN + project of x -> l1 (M, KP1) half -------------
__global__ void ln_project_kernel(const float* __restrict__ x,
                                  const float* __restrict__ lnw,
                                  const float* __restrict__ lnb,
                                  const float* __restrict__ bc,
                                  __half* __restrict__ out) {
    int row = blockIdx.x;
    int tid = threadIdx.x;
    const float* xr = x + (size_t)row * E_;
    __shared__ float red[32];
    float loc[4];
    float s = 0.f;
    #pragma unroll
    for (int u = 0; u < 4; ++u) { loc[u] = xr[tid + u * 256]; s += loc[u]; }
    float mean = block_reduce_sum(s, red) * (1.0f / E_);
    float vs = 0.f;
    #pragma unroll
    for (int u = 0; u < 4; ++u) { float d = loc[u] - mean; vs += d * d; }
    float var = block_reduce_sum(vs, red) * (1.0f / E_);
    float rstd = rsqrtf(var + 1e-5f);
    float Kb = expf(bc[0]);
    float ss = 0.f;
    __half* orow = out + (size_t)row * KP1;
    #pragma unroll
    for (int u = 0; u < 4; ++u) {
        int c = tid + u * 256;
        float y = (loc[u] - mean) * rstd * lnw[c] + lnb[c];
        orow[1 + c] = __float2half_rn(y);
        ss += y * y;
    }
    float sst = block_reduce_sum(ss, red);
    if (tid == 0) orow[0] = __float2half_rn(sqrtf(Kb + sst));
    if (tid < 63) orow[1025 + tid] = __float2half_rn(0.f);
}

// ---------------- kernel 3: RoPE + per-head norms (fp16 Q/K/V) ---------------
__global__ void rope_prep_kernel(const float* __restrict__ curv) {
    int tid = threadIdx.x;
    int lane = tid & 31;
    int rsub = tid >> 5;
    int r = blockIdx.x * 8 + rsub;            // r = bh*T + t
    int bh = r >> 11;
    int t  = r & (T_ - 1);
    int b  = bh >> 4;
    int h  = bh & 15;
    float Ka = expf(curv[h]);
    size_t base = ((size_t)(b * T_ + t)) * QKVN + h * D_;
    float q1 = __half2float(g_qkv[base + lane]);
    float q2 = __half2float(g_qkv[base + 32 + lane]);
    float k1 = __half2float(g_qkv[base + E_ + lane]);
    float k2 = __half2float(g_qkv[base + E_ + 32 + lane]);
    float v1 = __half2float(g_qkv[base + 2*E_ + lane]);
    float v2 = __half2float(g_qkv[base + 2*E_ + 32 + lane]);
    float inv = powf(10000.0f, -(float)lane * (1.0f / 32.0f));
    float fr = (float)t * inv;
    float sn, cs;
    sincosf(fr, &sn, &cs);
    __half qah = __float2half_rn(q1 * cs + q2 * sn);
    __half qbh = __float2half_rn(-q1 * sn + q2 * cs);
    __half kah = __float2half_rn(k1 * cs + k2 * sn);
    __half kbh = __float2half_rn(-k1 * sn + k2 * cs);
    float qa = __half2float(qah), qb = __half2float(qbh);
    float ka = __half2float(kah), kb = __half2float(kbh);
    float sq = qa * qa + qb * qb;
    float sk = ka * ka + kb * kb;
    float sv = v1 * v1 + v2 * v2;
    #pragma unroll
    for (int o = 16; o; o >>= 1) {
        sq += __shfl_xor_sync(0xffffffffu, sq, o);
        sk += __shfl_xor_sync(0xffffffffu, sk, o);
        sv += __shfl_xor_sync(0xffffffffu, sv, o);
    }
    size_t ob = ((size_t)bh * T_ + t) * D_;
    g_Q[ob + lane] = qah;  g_Q[ob + 32 + lane] = qbh;
    g_Kr[ob + lane] = kah; g_Kr[ob + 32 + lane] = kbh;
    g_V[ob + lane] = __float2half_rn(v1);
    g_V[ob + 32 + lane] = __float2half_rn(v2);
    if (lane == 0) {
        g_qt[r] = sqrtf(Ka + sq);
        g_kt[r] = sqrtf(Ka + sk);
        g_v0[r] = sqrtf(Ka + sv);
    }
}

// ---------------- kernel 4: hyperbolic causal attention (all-fp16 mma) -------
#define KVSTR 72                 // halves per K/V smem row (144 B, D=64 + pad)
#define PSCALE 1024.0f
#define RPSCALE (1.0f/1024.0f)
__global__ void __launch_bounds__(256, 2) attn_kernel(const float* __restrict__ curv) {
    __shared__ __align__(16) __half ksh[32 * KVSTR];
    __shared__ __align__(16) __half vsh[32 * KVSTR];
    __shared__ float kts[32], v0s[32];

    int bh = blockIdx.y;
    int b = bh >> 4, h = bh & 15;
    int q0 = blockIdx.x * 128;
    int tid = threadIdx.x, lane = tid & 31, w = tid >> 5;
    int grp = lane >> 2, tig = lane & 3;
    float Ka = expf(curv[h]);
    float sK = sqrtf(Ka);
    float rKa = 1.0f / Ka;
    float nsK = -sK;

    int r0 = q0 + w * 16 + grp;
    int r1 = r0 + 8;

    uint32_t kshaddr = smem_u32(ksh);
    uint32_t vshaddr = smem_u32(vsh);
    int q8 = lane >> 3, rr = lane & 7;
    uint32_t aoffK[2];
    #pragma unroll
    for (int j = 0; j < 2; ++j) {
        int nb = j * 16 + (q8 >> 1) * 8 + rr;
        aoffK[j] = kshaddr + (uint32_t)nb * (KVSTR * 2) + (q8 & 1) * 16;
    }
    uint32_t aoffV[4];
    {
        int krow = (q8 & 1) * 8 + rr;
        int ncol = (q8 >> 1) * 8;
        #pragma unroll
        for (int j = 0; j < 4; ++j)
            aoffV[j] = vshaddr + (uint32_t)(krow * KVSTR + j * 16 + ncol) * 2;
    }

    uint32_t qh[4][4];
    {
        const __half* Q0 = g_Q + ((size_t)bh * T_ + r0) * D_;
        const __half* Q1 = g_Q + ((size_t)bh * T_ + r1) * D_;
        #pragma unroll
        for (int ks = 0; ks < 4; ++ks) {
            qh[ks][0] = *(const uint32_t*)(Q0 + ks * 16 + 2 * tig);
            qh[ks][1] = *(const uint32_t*)(Q1 + ks * 16 + 2 * tig);
            qh[ks][2] = *(const uint32_t*)(Q0 + ks * 16 + 8 + 2 * tig);
            qh[ks][3] = *(const uint32_t*)(Q1 + ks * 16 + 8 + 2 * tig);
        }
    }
    float qt0 = g_qt[(size_t)bh * T_ + r0];
    float qt1 = g_qt[(size_t)bh * T_ + r1];

    float oacc[8][4];
    #pragma unroll
    for (int nb = 0; nb < 8; ++nb)
        #pragma unroll
        for (int cc = 0; cc < 4; ++cc) oacc[nb][cc] = 0.f;
    float ssum0 = 0.f, ssum1 = 0.f, o00 = 0.f, o01 = 0.f;

    for (int k0 = 0; k0 < q0 + 128; k0 += 32) {
        __syncthreads();
        {
            int rr2 = tid >> 3, c = tid & 7;
            *(uint4*)&ksh[rr2 * KVSTR + c * 8] =
                *(const uint4*)(g_Kr + ((size_t)bh * T_ + k0 + rr2) * D_ + c * 8);
            *(uint4*)&vsh[rr2 * KVSTR + c * 8] =
                *(const uint4*)(g_V + ((size_t)bh * T_ + k0 + rr2) * D_ + c * 8);
        }
        if (tid < 32) {
            kts[tid] = g_kt[(size_t)bh * T_ + k0 + tid];
            v0s[tid] = g_v0[(size_t)bh * T_ + k0 + tid];
        }
        __syncthreads();
        if (q0 + w * 16 + 15 < k0) continue;

        float sacc[4][4];
        #pragma unroll
        for (int nb = 0; nb < 4; ++nb)
            #pragma unroll
            for (int cc = 0; cc < 4; ++cc) sacc[nb][cc] = 0.f;
        #pragma unroll
        for (int ks = 0; ks < 4; ++ks) {
            uint32_t kofs = ks * 32;
            uint32_t bb[4][2];
            #pragma unroll
            for (int j = 0; j < 2; ++j) {
                uint32_t f0, f1, f2, f3;
                ldsm_x4(f0, f1, f2, f3, aoffK[j] + kofs);
                bb[2*j][0] = f0;   bb[2*j][1] = f1;
                bb[2*j+1][0] = f2; bb[2*j+1][1] = f3;
            }
            #pragma unroll
            for (int nb = 0; nb < 4; ++nb)
                mma_f16(sacc[nb], qh[ks], bb[nb]);
        }

        uint32_t ap[4][2];
        #pragma unroll
        for (int nb = 0; nb < 4; ++nb) {
            int cl = nb * 8 + 2 * tig;
            float ktc0 = kts[cl], ktc1 = kts[cl + 1];
            float v0c0 = v0s[cl], v0c1 = v0s[cl + 1];
            int cg0 = k0 + cl, cg1 = cg0 + 1;
            float p0, p1, p2, p3;
            {
                float ratio = fmaxf(-(sacc[nb][0] - qt0 * ktc0) * rKa, 1.0f + 1e-7f);
                float arg = ratio + sqrtf((ratio - 1.f) * (ratio + 1.f));
                p0 = (cg0 <= r0) ? __expf(nsK * __logf(arg)) : 0.f;
            }
            {
                float ratio = fmaxf(-(sacc[nb][1] - qt0 * ktc1) * rKa, 1.0f + 1e-7f);
                float arg = ratio + sqrtf((ratio - 1.f) * (ratio + 1.f));
                p1 = (cg1 <= r0) ? __expf(nsK * __logf(arg)) : 0.f;
            }
            {
                float ratio = fmaxf(-(sacc[nb][2] - qt1 * ktc0) * rKa, 1.0f + 1e-7f);
                float arg = ratio + sqrtf((ratio - 1.f) * (ratio + 1.f));
                p2 = (cg0 <= r1) ? __expf(nsK * __logf(arg)) : 0.f;
            }
            {
                float ratio = fmaxf(-(sacc[nb][3] - qt1 * ktc1) * rKa, 1.0f + 1e-7f);
                float arg = ratio + sqrtf((ratio - 1.f) * (ratio + 1.f));
                p3 = (cg1 <= r1) ? __expf(nsK * __logf(arg)) : 0.f;
            }
            ssum0 += p0 + p1;  o00 += p0 * v0c0 + p1 * v0c1;
            ssum1 += p2 + p3;  o01 += p2 * v0c0 + p3 * v0c1;
            __half2 h01 = __floats2half2_rn(p0 * PSCALE, p1 * PSCALE);
            __half2 h23 = __floats2half2_rn(p2 * PSCALE, p3 * PSCALE);
            ap[nb][0] = *(uint32_t*)&h01;
            ap[nb][1] = *(uint32_t*)&h23;
        }

        #pragma unroll
        for (int ks = 0; ks < 2; ++ks) {
            uint32_t A[4] = { ap[2*ks][0], ap[2*ks][1], ap[2*ks+1][0], ap[2*ks+1][1] };
            uint32_t vofs = ks * (16 * KVSTR * 2);
            #pragma unroll
            for (int j = 0; j < 4; ++j) {
                uint32_t f0, f1, f2, f3;
                ldsm_x4_t(f0, f1, f2, f3, aoffV[j] + vofs);
                uint32_t B0[2] = { f0, f1 };
                uint32_t B1[2] = { f2, f3 };
                mma_f16(oacc[2*j],     A, B0);
                mma_f16(oacc[2*j + 1], A, B1);
            }
        }
    }

    #pragma unroll
    for (int m = 1; m < 4; m <<= 1) {
        ssum0 += __shfl_xor_sync(0xffffffffu, ssum0, m);
        ssum1 += __shfl_xor_sync(0xffffffffu, ssum1, m);
        o00   += __shfl_xor_sync(0xffffffffu, o00, m);
        o01   += __shfl_xor_sync(0xffffffffu, o01, m);
    }
    float rs0 = 1.0f / ssum0, rs1 = 1.0f / ssum1;
    float on0 = o00 * rs0, on1 = o01 * rs1;
    float rso0 = rs0 * RPSCALE, rso1 = rs1 * RPSCALE;
    float s20 = 0.f, s21 = 0.f;
    #pragma unroll
    for (int nb = 0; nb < 8; ++nb) {
        float a0 = oacc[nb][0] * rso0, a1 = oacc[nb][1] * rso0;
        float a2 = oacc[nb][2] * rso1, a3 = oacc[nb][3] * rso1;
        oacc[nb][0] = a0; oacc[nb][1] = a1; oacc[nb][2] = a2; oacc[nb][3] = a3;
        s20 += a0 * a0 + a1 * a1;
        s21 += a2 * a2 + a3 * a3;
    }
    #pragma unroll
    for (int m = 1; m < 4; m <<= 1) {
        s20 += __shfl_xor_sync(0xffffffffu, s20, m);
        s21 += __shfl_xor_sync(0xffffffffu, s21, m);
    }
    float hn0 = sqrtf(fmaxf(on0 * on0 - s20, 1e-12f));
    float hn1 = sqrtf(fmaxf(on1 * on1 - s21, 1e-12f));
    float sc0 = sK / hn0, sc1 = sK / hn1;

    __half* base0 = g_o + ((size_t)(b * T_ + r0)) * KP1 + h * 65;
    __half* base1 = g_o + ((size_t)(b * T_ + r1)) * KP1 + h * 65;
    if (tig == 0) {
        base0[0] = __float2half_rn(on0 * sc0);
        base1[0] = __float2half_rn(on1 * sc1);
    }
    #pragma unroll
    for (int nb = 0; nb < 8; ++nb) {
        int c = nb * 8 + 2 * tig;
        base0[1 + c]     = __float2half_rn(oacc[nb][0] * sc0);
        base0[1 + c + 1] = __float2half_rn(oacc[nb][1] * sc0);
        base1[1 + c]     = __float2half_rn(oacc[nb][2] * sc1);
        base1[1 + c + 1] = __float2half_rn(oacc[nb][3] * sc1);
    }
    if (h == 15) {               // zero pad cols 1040..1087
        __half* pr0 = g_o + ((size_t)(b * T_ + r0)) * KP1;
        __half* pr1 = g_o + ((size_t)(b * T_ + r1)) * KP1;
        #pragma unroll
        for (int i = 0; i < 12; ++i) {
            pr0[1040 + tig * 12 + i] = __float2half_rn(0.f);
            pr1[1040 + tig * 12 + i] = __float2half_rn(0.f);
        }
    }
}

// ---------------- kernel 6: LN + project of y1 -> l2 --------------------------
__global__ void resid_ln_project_kernel(const float* __restrict__ lnw,
                                        const float* __restrict__ lnb,
                                        const float* __restrict__ bc) {
    int row = blockIdx.x;
    int tid = threadIdx.x;
    const float* yr = g_y1 + (size_t)row * E_;
    __shared__ float red[32];
    float loc[4];
    float s = 0.f;
    #pragma unroll
    for (int u = 0; u < 4; ++u) {
        loc[u] = yr[tid + u * 256];
        s += loc[u];
    }
    float mean = block_reduce_sum(s, red) * (1.0f / E_);
    float vs = 0.f;
    #pragma unroll
    for (int u = 0; u < 4; ++u) { float d = loc[u] - mean; vs += d * d; }
    float var = block_reduce_sum(vs, red) * (1.0f / E_);
    float rstd = rsqrtf(var + 1e-5f);
    float Kb = expf(bc[0]);
    float ss = 0.f;
    __half* orow = g_l2 + (size_t)row * KP1;
    #pragma unroll
    for (int u = 0; u < 4; ++u) {
        int c = tid + u * 256;
        float y = (loc[u] - mean) * rstd * lnw[c] + lnb[c];
        orow[1 + c] = __float2half_rn(y);
        ss += y * y;
    }
    float sst = block_reduce_sum(ss, red);
    if (tid == 0) orow[0] = __float2half_rn(sqrtf(Kb + sst));
    if (tid < 63) orow[1025 + tid] = __float2half_rn(0.f);
}

// ---------------- kernel 8: hp row norm (reads fused-gelu half output) -------
__global__ void hp_norm_kernel(const float* __restrict__ mc) {
    int row = blockIdx.x;
    int tid = threadIdx.x;
    __half* op = g_hp + (size_t)row * KP4;
    __shared__ float red[32];
    float Km = expf(mc[0]);
    float ss = 0.f;
    for (int c = tid; c < MEXP; c += 256) {
        float g = __half2float(op[1 + c]);
        ss += g * g;
    }
    float sst = block_reduce_sum(ss, red);
    if (tid == 0) op[0] = __float2half_rn(sqrtf(Km + sst));
    if (tid < 60) op[4100 + tid] = __float2half_rn(0.f);
}

// ---------------- kernel 10: final norm column (out[.,1..] already written) --
__global__ void final_norm_kernel(const float* __restrict__ bc,
                                  float* __restrict__ out) {
    int row = blockIdx.x;
    int tid = threadIdx.x;
    float* orow = out + (size_t)row * (E_ + 1);
    __shared__ float red[32];
    float Kb = expf(bc[0]);
    float ss = 0.f;
    #pragma unroll
    for (int u = 0; u < 4; ++u) {
        float y = orow[1 + tid + u * 256];
        ss += y * y;
    }
    float sst = block_reduce_sum(ss, red);
    if (tid == 0) orow[0] = sqrtf(Kb + sst);
}

// ---------------- launch -----------------------------------------------------
extern "C" void kernel_launch(void* const* d_in, const int* in_sizes, int n_in,
                              void* d_out, int out_size) {
    const float* x      = (const float*)d_in[0];
    const float* bc     = (const float*)d_in[1];
    const float* mc     = (const float*)d_in[2];
    const float* acurv  = (const float*)d_in[3];
    const float* w_qkv  = (const float*)d_in[4];
    const float* w_ap   = (const float*)d_in[5];
    const float* b_ap   = (const float*)d_in[6];
    const float* w_me   = (const float*)d_in[7];
    const float* b_me   = (const float*)d_in[8];
    const float* w_ms   = (const float*)d_in[9];
    const float* b_ms   = (const float*)d_in[10];
    const float* lnw    = (const float*)d_in[11];
    const float* lnb    = (const float*)d_in[12];
    float* out = (float*)d_out;

    __half *p_l1, *p_qkv, *p_o, *p_l2, *p_hp, *p_wq, *p_wa, *p_we, *p_ws;
    float  *p_y1;
    cudaGetSymbolAddress((void**)&p_l1,  g_l1);
    cudaGetSymbolAddress((void**)&p_qkv, g_qkv);
    cudaGetSymbolAddress((void**)&p_o,   g_o);
    cudaGetSymbolAddress((void**)&p_y1,  g_y1);
    cudaGetSymbolAddress((void**)&p_l2,  g_l2);
    cudaGetSymbolAddress((void**)&p_hp,  g_hp);
    cudaGetSymbolAddress((void**)&p_wq,  g_wt_qkv);
    cudaGetSymbolAddress((void**)&p_wa,  g_wt_ap);
    cudaGetSymbolAddress((void**)&p_we,  g_wt_me);
    cudaGetSymbolAddress((void**)&p_ws,  g_wt_ms);

    const int GSMEM = 4 * HBYTES;   // 73728 bytes
    cudaFuncSetAttribute(gemm_f16_kernel,
                         cudaFuncAttributeMaxDynamicSharedMemorySize, GSMEM);

    transpose_all_kernel<<<TC0 + TC1 + TC2 + TC3, dim3(32, 8)>>>(
        w_qkv, w_ap, w_me, w_ms);

    ln_project_kernel<<<MROWS, 256>>>(x, lnw, lnb, bc, p_l1);
    // qkv = l1 @ Wqkv (half out)
    gemm_f16_kernel<<<dim3(QKVN/128, MROWS/128), 256, GSMEM>>>(
        p_l1, KP1, p_wq, KP1, nullptr, p_qkv, QKVN, QKVN, KP1/64, 2, nullptr);
    rope_prep_kernel<<<(B_ * H_ * T_) / 8, 256>>>(acurv);
    attn_kernel<<<dim3(T_ / 128, B_ * H_), 256>>>(acurv);
    // y1 = o @ Wap + b_ap + x  (fp32, fused residual)
    gemm_f16_kernel<<<dim3(E_/128, MROWS/128), 256, GSMEM>>>(
        p_o, KP1, p_wa, KP1, b_ap, p_y1, E_, E_, KP1/64, 3, x);
    resid_ln_project_kernel<<<MROWS, 256>>>(lnw, lnb, bc);
    // hp[.,1+c] = gelu(l2 @ Wme + b_me)  (half, fused gelu)
    gemm_f16_kernel<<<dim3(NP_ME/128, MROWS/128), 256, GSMEM>>>(
        p_l2, KP1, p_we, KP1, b_me, p_hp, KP4, MEXP, KP1/64, 1, nullptr);
    hp_norm_kernel<<<MROWS, 256>>>(mc);
    // out[.,1+c] = hp @ Wms + b_ms + y1  (fp32, fused residual, strided into out)
    gemm_f16_kernel<<<dim3(E_/128, MROWS/128), 256, GSMEM>>>(
        p_hp, KP4, p_ws, KP4, b_ms, out + 1, E_ + 1, E_, KP4/64, 4, p_y1);
    final_norm_kernel<<<MROWS, 256>>>(bc, out);
}

// round 14
// speedup vs baseline: 1.4545x; 1.4545x over previous
#include <cuda_runtime.h>
#include <cuda_fp16.h>
#include <math.h>
#include <stdint.h>

// Problem dims
#define B_  2
#define T_  2048
#define E_  1024
#define H_  16
#define D_  64
#define MROWS (B_*T_)            // 4096
#define QKVN  (3*E_)             // 3072
#define MEXP  4099               // 4E+3
// padded K dims for tensor-core GEMMs (multiples of 32)
#define KP1   1056               // pads 1025 and 1040
#define KP4   4128               // pads 4100
#define NP_ME 4224               // padded N for mlp expand (4099 -> 33*128)

// ---------------- scratch (static device globals; no allocation) -------------
__device__ __half g_l1 [MROWS*KP1];
__device__ __half g_qkv[MROWS*QKVN];
__device__ __half g_Q  [B_*H_*T_*D_];
__device__ __half g_Kr [B_*H_*T_*D_];
__device__ __half g_V  [B_*H_*T_*D_];
__device__ float  g_qt [B_*H_*T_];
__device__ float  g_kt [B_*H_*T_];
__device__ float  g_v0 [B_*H_*T_];
__device__ __half g_o  [MROWS*KP1];
__device__ float  g_y1 [MROWS*E_];
__device__ __half g_l2 [MROWS*KP1];
__device__ __half g_hp [MROWS*KP4];
// transposed + fp16-rounded + zero-padded weights: Wt[N,K]
__device__ __half g_wt_qkv[QKVN*KP1];
__device__ __half g_wt_ap [E_*KP1];
__device__ __half g_wt_me [NP_ME*KP1];
__device__ __half g_wt_ms [E_*KP4];

// ---------------- helpers -----------------------------------------------------
__device__ __forceinline__ uint32_t smem_u32(const void* p) {
    uint32_t a;
    asm("{ .reg .u64 t; cvta.to.shared.u64 t, %1; cvt.u32.u64 %0, t; }" : "=r"(a) : "l"(p));
    return a;
}
#define CP_ASYNC16(dst, src) \
    asm volatile("cp.async.cg.shared.global [%0], [%1], 16;" :: "r"(dst), "l"(src))
#define CP_COMMIT()  asm volatile("cp.async.commit_group;")
#define CP_WAIT(n)   asm volatile("cp.async.wait_group %0;" :: "n"(n))

// fp16 mma, fp32 accumulate
__device__ __forceinline__ void mma_f16(float* c, const uint32_t* a, const uint32_t* b) {
    asm volatile(
        "mma.sync.aligned.m16n8k16.row.col.f32.f16.f16.f32 "
        "{%0,%1,%2,%3}, {%4,%5,%6,%7}, {%8,%9}, {%0,%1,%2,%3};"
        : "+f"(c[0]), "+f"(c[1]), "+f"(c[2]), "+f"(c[3])
        : "r"(a[0]), "r"(a[1]), "r"(a[2]), "r"(a[3]), "r"(b[0]), "r"(b[1]));
}
__device__ __forceinline__ void ldsm_x4(uint32_t& r0, uint32_t& r1,
                                        uint32_t& r2, uint32_t& r3, uint32_t addr) {
    asm volatile("ldmatrix.sync.aligned.m8n8.x4.shared.b16 {%0,%1,%2,%3}, [%4];"
        : "=r"(r0), "=r"(r1), "=r"(r2), "=r"(r3) : "r"(addr));
}
__device__ __forceinline__ void ldsm_x4_t(uint32_t& r0, uint32_t& r1,
                                          uint32_t& r2, uint32_t& r3, uint32_t addr) {
    asm volatile("ldmatrix.sync.aligned.m8n8.x4.trans.shared.b16 {%0,%1,%2,%3}, [%4];"
        : "=r"(r0), "=r"(r1), "=r"(r2), "=r"(r3) : "r"(addr));
}

__device__ __forceinline__ float block_reduce_sum(float v, float* red) {
    int tid = threadIdx.x;
    #pragma unroll
    for (int o = 16; o; o >>= 1) v += __shfl_xor_sync(0xffffffffu, v, o);
    if ((tid & 31) == 0) red[tid >> 5] = v;
    __syncthreads();
    float r = (tid < (int)(blockDim.x >> 5)) ? red[tid] : 0.f;
    if (tid < 32) {
        #pragma unroll
        for (int o = 16; o; o >>= 1) r += __shfl_xor_sync(0xffffffffu, r, o);
        if (tid == 0) red[0] = r;
    }
    __syncthreads();
    float out = red[0];
    __syncthreads();
    return out;
}

// ---------------- merged weight transpose + fp16 round + zero pad ------------
#define TC0 (33*96)     // qkv : K=1025 N=3072 Kpad=KP1
#define TC1 (33*32)     // ap  : K=1040 N=1024 Kpad=KP1
#define TC2 (33*132)    // me  : K=1025 N=4099 Kpad=KP1, Npad=4224
#define TC3 (129*32)    // ms  : K=4100 N=1024 Kpad=KP4
__global__ void transpose_all_kernel(const float* __restrict__ w_qkv,
                                     const float* __restrict__ w_ap,
                                     const float* __restrict__ w_me,
                                     const float* __restrict__ w_ms) {
    __shared__ float s[32][33];
    int id = blockIdx.x;
    const float* W; __half* Wt;
    int K, N, Kpad, nx, r;
    if (id < TC0)                  { r = id;                W = w_qkv; Wt = g_wt_qkv; K = 1025; N = 3072; Kpad = KP1; nx = 33; }
    else if (id < TC0+TC1)         { r = id - TC0;          W = w_ap;  Wt = g_wt_ap;  K = 1040; N = 1024; Kpad = KP1; nx = 33; }
    else if (id < TC0+TC1+TC2)     { r = id - TC0 - TC1;    W = w_me;  Wt = g_wt_me;  K = 1025; N = 4099; Kpad = KP1; nx = 33; }
    else                           { r = id - TC0 - TC1-TC2;W = w_ms;  Wt = g_wt_ms;  K = 4100; N = 1024; Kpad = KP4; nx = 129; }
    int k0 = (r % nx) * 32, n0 = (r / nx) * 32;
    int tx = threadIdx.x, ty = threadIdx.y;          // 32 x 8
    #pragma unroll
    for (int yy = ty; yy < 32; yy += 8) {
        int k = k0 + yy, n = n0 + tx;
        float v = (k < K && n < N) ? W[(size_t)k * N + n] : 0.f;
        s[yy][tx] = v;
    }
    __syncthreads();
    #pragma unroll
    for (int yy = ty; yy < 32; yy += 8) {
        int n = n0 + yy, k = k0 + tx;
        Wt[(size_t)n * Kpad + k] = __float2half_rn(s[tx][yy]);
    }
}

// ---------------- fp16 tensor-core GEMM (mma.sync m16n8k16 + ldmatrix) --------
// BK=32 (R12-proven). modes:
//  1: C(half)[r*ldc + 1 + c] = fp16(gelu(acc + bias))
//  2: C(half)[r*ldc + c]     = fp16(acc + bias)
//  3/4: C(float)[r*ldc + c]  = acc + bias + X2[r*E_ + c]   (fused residual)
#define HSTR 40                      // halves per SMEM row (80 B) — conflict-free
#define HBUF (128*HSTR)              // halves per buffer
#define HBYTES (HBUF*2)              // bytes per buffer (10240)
__global__ void __launch_bounds__(256, 2) gemm_f16_kernel(
        const __half* __restrict__ A, int lda,
        const __half* __restrict__ Bt, int ldb,
        const float* __restrict__ bias,
        void* __restrict__ Cv, int ldc, int Nact, int nchunks, int mode,
        const float* __restrict__ X2) {
    extern __shared__ __half hsm[];
    uint32_t smaddr = smem_u32(hsm);
    int tid = threadIdx.x;
    int lane = tid & 31, w = tid >> 5;
    int grp = lane >> 2, tig = lane & 3;
    int wm = w >> 1, wn = w & 1;
    int row0 = blockIdx.y * 128, col0 = blockIdx.x * 128;

    int q8 = lane >> 3, rr = lane & 7;
    uint32_t aoffA[2], aoffB[4];
    #pragma unroll
    for (int mi = 0; mi < 2; ++mi) {
        int rowa = wm * 32 + mi * 16 + (q8 & 1) * 8 + rr;
        aoffA[mi] = smaddr + (uint32_t)rowa * (HSTR * 2) + (q8 >> 1) * 16;
    }
    #pragma unroll
    for (int j = 0; j < 4; ++j) {
        int nb = wn * 64 + j * 16 + (q8 >> 1) * 8 + rr;
        aoffB[j] = smaddr + 2 * HBYTES + (uint32_t)nb * (HSTR * 2) + (q8 & 1) * 16;
    }

    float acc[2][8][4];
    #pragma unroll
    for (int mi = 0; mi < 2; ++mi)
        #pragma unroll
        for (int ni = 0; ni < 8; ++ni)
            #pragma unroll
            for (int cc = 0; cc < 4; ++cc) acc[mi][ni][cc] = 0.f;

    const __half* Arow = A  + (size_t)row0 * lda;
    const __half* Brow = Bt + (size_t)col0 * ldb;

    auto load_chunk = [&](int buf, int kc) {
        int k0 = kc * 32;
        uint32_t abase = smaddr + buf * HBYTES;
        uint32_t bbase = smaddr + 2 * HBYTES + buf * HBYTES;
        #pragma unroll
        for (int u = 0; u < 2; ++u) {
            int idx = tid + u * 256;             // 0..511
            int r = idx >> 2, c = idx & 3;       // 128 rows x 4 16B-chunks
            CP_ASYNC16(abase + r * (HSTR * 2) + c * 16,
                       Arow + (size_t)r * lda + k0 + c * 8);
            CP_ASYNC16(bbase + r * (HSTR * 2) + c * 16,
                       Brow + (size_t)r * ldb + k0 + c * 8);
        }
        CP_COMMIT();
    };

    load_chunk(0, 0);
    for (int i = 0; i < nchunks; ++i) {
        int buf = i & 1;
        if (i + 1 < nchunks) { load_chunk(buf ^ 1, i + 1); CP_WAIT(1); }
        else                 { CP_WAIT(0); }
        __syncthreads();
        uint32_t bufofs = buf * HBYTES;
        #pragma unroll
        for (int ks = 0; ks < 2; ++ks) {
            uint32_t kofs = bufofs + ks * 32;
            uint32_t a[2][4];
            ldsm_x4(a[0][0], a[0][1], a[0][2], a[0][3], aoffA[0] + kofs);
            ldsm_x4(a[1][0], a[1][1], a[1][2], a[1][3], aoffA[1] + kofs);
            uint32_t b[8][2];
            #pragma unroll
            for (int j = 0; j < 4; ++j) {
                uint32_t r0, r1, r2, r3;
                ldsm_x4(r0, r1, r2, r3, aoffB[j] + kofs);
                b[2*j][0] = r0;   b[2*j][1] = r1;
                b[2*j+1][0] = r2; b[2*j+1][1] = r3;
            }
            #pragma unroll
            for (int mi = 0; mi < 2; ++mi)
                #pragma unroll
                for (int ni = 0; ni < 8; ++ni)
                    mma_f16(acc[mi][ni], a[mi], b[ni]);
        }
        __syncthreads();
    }

    if (mode == 2) {
        __half* C = (__half*)Cv;
        #pragma unroll
        for (int mi = 0; mi < 2; ++mi) {
            int rbase = row0 + wm * 32 + mi * 16 + grp;
            #pragma unroll
            for (int ni = 0; ni < 8; ++ni) {
                int gc = col0 + wn * 64 + ni * 8 + tig * 2;
                if (gc < Nact) {
                    float b0 = bias ? bias[gc] : 0.f;
                    float b1 = (bias && gc + 1 < Nact) ? bias[gc + 1] : 0.f;
                    __half* p0 = C + (size_t)rbase * ldc + gc;
                    __half* p1 = C + (size_t)(rbase + 8) * ldc + gc;
                    p0[0] = __float2half_rn(acc[mi][ni][0] + b0);
                    if (gc + 1 < Nact) p0[1] = __float2half_rn(acc[mi][ni][1] + b1);
                    p1[0] = __float2half_rn(acc[mi][ni][2] + b0);
                    if (gc + 1 < Nact) p1[1] = __float2half_rn(acc[mi][ni][3] + b1);
                }
            }
        }
    } else if (mode == 1) {
        __half* C = (__half*)Cv;
        #pragma unroll
        for (int mi = 0; mi < 2; ++mi) {
            int rbase = row0 + wm * 32 + mi * 16 + grp;
            #pragma unroll
            for (int ni = 0; ni < 8; ++ni) {
                int gc = col0 + wn * 64 + ni * 8 + tig * 2;
                if (gc < Nact) {
                    float b0 = bias ? bias[gc] : 0.f;
                    float b1 = (bias && gc + 1 < Nact) ? bias[gc + 1] : 0.f;
                    float v0 = acc[mi][ni][0] + b0;
                    float v1 = acc[mi][ni][1] + b1;
                    float v2 = acc[mi][ni][2] + b0;
                    float v3 = acc[mi][ni][3] + b1;
                    float g0 = 0.5f * v0 * (1.0f + erff(v0 * 0.70710678118654752f));
                    float g1 = 0.5f * v1 * (1.0f + erff(v1 * 0.70710678118654752f));
                    float g2 = 0.5f * v2 * (1.0f + erff(v2 * 0.70710678118654752f));
                    float g3 = 0.5f * v3 * (1.0f + erff(v3 * 0.70710678118654752f));
                    __half* p0 = C + (size_t)rbase * ldc + 1 + gc;
                    __half* p1 = C + (size_t)(rbase + 8) * ldc + 1 + gc;
                    p0[0] = __float2half_rn(g0);
                    if (gc + 1 < Nact) p0[1] = __float2half_rn(g1);
                    p1[0] = __float2half_rn(g2);
                    if (gc + 1 < Nact) p1[1] = __float2half_rn(g3);
                }
            }
        }
    } else {   // modes 3/4: fp32 out with fused residual add (X2 stride E_)
        float* C = (float*)Cv;
        #pragma unroll
        for (int mi = 0; mi < 2; ++mi) {
            int rbase = row0 + wm * 32 + mi * 16 + grp;
            #pragma unroll
            for (int ni = 0; ni < 8; ++ni) {
                int gc = col0 + wn * 64 + ni * 8 + tig * 2;
                if (gc < Nact) {
                    float b0 = bias ? bias[gc] : 0.f;
                    float b1 = (bias && gc + 1 < Nact) ? bias[gc + 1] : 0.f;
                    const float* x0 = X2 + (size_t)rbase * E_ + gc;
                    const float* x1 = X2 + (size_t)(rbase + 8) * E_ + gc;
                    float* p0 = C + (size_t)rbase * ldc + gc;
                    float* p1 = C + (size_t)(rbase + 8) * ldc + gc;
                    p0[0] = acc[mi][ni][0] + b0 + x0[0];
                    if (gc + 1 < Nact) p0[1] = acc[mi][ni][1] + b1 + x0[1];
                    p1[0] = acc[mi][ni][2] + b0 + x1[0];
                    if (gc + 1 < Nact) p1[1] = acc[mi][ni][3] + b1 + x1[1];
                }
            }
        }
    }
}

// ---------------- kernel 1: LN + project of x -> l1 (M, KP1) half -------------
__global__ void ln_project_kernel(const float* __restrict__ x,
                                  const float* __restrict__ lnw,
                                  const float* __restrict__ lnb,
                                  const float* __restrict__ bc,
                                  __half* __restrict__ out) {
    int row = blockIdx.x;
    int tid = threadIdx.x;
    const float* xr = x + (size_t)row * E_;
    __shared__ float red[32];
    float loc[4];
    float s = 0.f;
    #pragma unroll
    for (int u = 0; u < 4; ++u) { loc[u] = xr[tid + u * 256]; s += loc[u]; }
    float mean = block_reduce_sum(s, red) * (1.0f / E_);
    float vs = 0.f;
    #pragma unroll
    for (int u = 0; u < 4; ++u) { float d = loc[u] - mean; vs += d * d; }
    float var = block_reduce_sum(vs, red) * (1.0f / E_);
    float rstd = rsqrtf(var + 1e-5f);
    float Kb = expf(bc[0]);
    float ss = 0.f;
    __half* orow = out + (size_t)row * KP1;
    #pragma unroll
    for (int u = 0; u < 4; ++u) {
        int c = tid + u * 256;
        float y = (loc[u] - mean) * rstd * lnw[c] + lnb[c];
        orow[1 + c] = __float2half_rn(y);
        ss += y * y;
    }
    float sst = block_reduce_sum(ss, red);
    if (tid == 0) orow[0] = __float2half_rn(sqrtf(Kb + sst));
    if (tid < 31) orow[1025 + tid] = __float2half_rn(0.f);
}

// ---------------- kernel 3: RoPE + per-head norms (fp16 Q/K/V) ---------------
__global__ void rope_prep_kernel(const float* __restrict__ curv) {
    int tid = threadIdx.x;
    int lane = tid & 31;
    int rsub = tid >> 5;
    int r = blockIdx.x * 8 + rsub;            // r = bh*T + t
    int bh = r >> 11;
    int t  = r & (T_ - 1);
    int b  = bh >> 4;
    int h  = bh & 15;
    float Ka = expf(curv[h]);
    size_t base = ((size_t)(b * T_ + t)) * QKVN + h * D_;
    float q1 = __half2float(g_qkv[base + lane]);
    float q2 = __half2float(g_qkv[base + 32 + lane]);
    float k1 = __half2float(g_qkv[base + E_ + lane]);
    float k2 = __half2float(g_qkv[base + E_ + 32 + lane]);
    float v1 = __half2float(g_qkv[base + 2*E_ + lane]);
    float v2 = __half2float(g_qkv[base + 2*E_ + 32 + lane]);
    float inv = powf(10000.0f, -(float)lane * (1.0f / 32.0f));
    float fr = (float)t * inv;
    float sn, cs;
    sincosf(fr, &sn, &cs);
    __half qah = __float2half_rn(q1 * cs + q2 * sn);
    __half qbh = __float2half_rn(-q1 * sn + q2 * cs);
    __half kah = __float2half_rn(k1 * cs + k2 * sn);
    __half kbh = __float2half_rn(-k1 * sn + k2 * cs);
    float qa = __half2float(qah), qb = __half2float(qbh);
    float ka = __half2float(kah), kb = __half2float(kbh);
    float sq = qa * qa + qb * qb;
    float sk = ka * ka + kb * kb;
    float sv = v1 * v1 + v2 * v2;
    #pragma unroll
    for (int o = 16; o; o >>= 1) {
        sq += __shfl_xor_sync(0xffffffffu, sq, o);
        sk += __shfl_xor_sync(0xffffffffu, sk, o);
        sv += __shfl_xor_sync(0xffffffffu, sv, o);
    }
    size_t ob = ((size_t)bh * T_ + t) * D_;
    g_Q[ob + lane] = qah;  g_Q[ob + 32 + lane] = qbh;
    g_Kr[ob + lane] = kah; g_Kr[ob + 32 + lane] = kbh;
    g_V[ob + lane] = __float2half_rn(v1);
    g_V[ob + 32 + lane] = __float2half_rn(v2);
    if (lane == 0) {
        g_qt[r] = sqrtf(Ka + sq);
        g_kt[r] = sqrtf(Ka + sk);
        g_v0[r] = sqrtf(Ka + sv);
    }
}

// ---------------- kernel 4: hyperbolic causal attention (all-fp16 mma) -------
#define KVSTR 72                 // halves per K/V smem row (144 B, D=64 + pad)
#define PSCALE 1024.0f
#define RPSCALE (1.0f/1024.0f)
__global__ void __launch_bounds__(256, 2) attn_kernel(const float* __restrict__ curv) {
    __shared__ __align__(16) __half ksh[32 * KVSTR];
    __shared__ __align__(16) __half vsh[32 * KVSTR];
    __shared__ float kts[32], v0s[32];

    int bh = blockIdx.y;
    int b = bh >> 4, h = bh & 15;
    int q0 = blockIdx.x * 128;
    int tid = threadIdx.x, lane = tid & 31, w = tid >> 5;
    int grp = lane >> 2, tig = lane & 3;
    float Ka = expf(curv[h]);
    float sK = sqrtf(Ka);
    float rKa = 1.0f / Ka;
    float nsK = -sK;

    int r0 = q0 + w * 16 + grp;
    int r1 = r0 + 8;

    uint32_t kshaddr = smem_u32(ksh);
    uint32_t vshaddr = smem_u32(vsh);
    int q8 = lane >> 3, rr = lane & 7;
    uint32_t aoffK[2];
    #pragma unroll
    for (int j = 0; j < 2; ++j) {
        int nb = j * 16 + (q8 >> 1) * 8 + rr;
        aoffK[j] = kshaddr + (uint32_t)nb * (KVSTR * 2) + (q8 & 1) * 16;
    }
    uint32_t aoffV[4];
    {
        int krow = (q8 & 1) * 8 + rr;
        int ncol = (q8 >> 1) * 8;
        #pragma unroll
        for (int j = 0; j < 4; ++j)
            aoffV[j] = vshaddr + (uint32_t)(krow * KVSTR + j * 16 + ncol) * 2;
    }

    uint32_t qh[4][4];
    {
        const __half* Q0 = g_Q + ((size_t)bh * T_ + r0) * D_;
        const __half* Q1 = g_Q + ((size_t)bh * T_ + r1) * D_;
        #pragma unroll
        for (int ks = 0; ks < 4; ++ks) {
            qh[ks][0] = *(const uint32_t*)(Q0 + ks * 16 + 2 * tig);
            qh[ks][1] = *(const uint32_t*)(Q1 + ks * 16 + 2 * tig);
            qh[ks][2] = *(const uint32_t*)(Q0 + ks * 16 + 8 + 2 * tig);
            qh[ks][3] = *(const uint32_t*)(Q1 + ks * 16 + 8 + 2 * tig);
        }
    }
    float qt0 = g_qt[(size_t)bh * T_ + r0];
    float qt1 = g_qt[(size_t)bh * T_ + r1];

    float oacc[8][4];
    #pragma unroll
    for (int nb = 0; nb < 8; ++nb)
        #pragma unroll
        for (int cc = 0; cc < 4; ++cc) oacc[nb][cc] = 0.f;
    float ssum0 = 0.f, ssum1 = 0.f, o00 = 0.f, o01 = 0.f;

    for (int k0 = 0; k0 < q0 + 128; k0 += 32) {
        __syncthreads();
        {
            int rr2 = tid >> 3, c = tid & 7;
            *(uint4*)&ksh[rr2 * KVSTR + c * 8] =
                *(const uint4*)(g_Kr + ((size_t)bh * T_ + k0 + rr2) * D_ + c * 8);
            *(uint4*)&vsh[rr2 * KVSTR + c * 8] =
                *(const uint4*)(g_V + ((size_t)bh * T_ + k0 + rr2) * D_ + c * 8);
        }
        if (tid < 32) {
            kts[tid] = g_kt[(size_t)bh * T_ + k0 + tid];
            v0s[tid] = g_v0[(size_t)bh * T_ + k0 + tid];
        }
        __syncthreads();
        if (q0 + w * 16 + 15 < k0) continue;

        float sacc[4][4];
        #pragma unroll
        for (int nb = 0; nb < 4; ++nb)
            #pragma unroll
            for (int cc = 0; cc < 4; ++cc) sacc[nb][cc] = 0.f;
        #pragma unroll
        for (int ks = 0; ks < 4; ++ks) {
            uint32_t kofs = ks * 32;
            uint32_t bb[4][2];
            #pragma unroll
            for (int j = 0; j < 2; ++j) {
                uint32_t f0, f1, f2, f3;
                ldsm_x4(f0, f1, f2, f3, aoffK[j] + kofs);
                bb[2*j][0] = f0;   bb[2*j][1] = f1;
                bb[2*j+1][0] = f2; bb[2*j+1][1] = f3;
            }
            #pragma unroll
            for (int nb = 0; nb < 4; ++nb)
                mma_f16(sacc[nb], qh[ks], bb[nb]);
        }

        uint32_t ap[4][2];
        #pragma unroll
        for (int nb = 0; nb < 4; ++nb) {
            int cl = nb * 8 + 2 * tig;
            float ktc0 = kts[cl], ktc1 = kts[cl + 1];
            float v0c0 = v0s[cl], v0c1 = v0s[cl + 1];
            int cg0 = k0 + cl, cg1 = cg0 + 1;
            float p0, p1, p2, p3;
            {
                float ratio = fmaxf(-(sacc[nb][0] - qt0 * ktc0) * rKa, 1.0f + 1e-7f);
                float arg = ratio + sqrtf((ratio - 1.f) * (ratio + 1.f));
                p0 = (cg0 <= r0) ? __expf(nsK * __logf(arg)) : 0.f;
            }
            {
                float ratio = fmaxf(-(sacc[nb][1] - qt0 * ktc1) * rKa, 1.0f + 1e-7f);
                float arg = ratio + sqrtf((ratio - 1.f) * (ratio + 1.f));
                p1 = (cg1 <= r0) ? __expf(nsK * __logf(arg)) : 0.f;
            }
            {
                float ratio = fmaxf(-(sacc[nb][2] - qt1 * ktc0) * rKa, 1.0f + 1e-7f);
                float arg = ratio + sqrtf((ratio - 1.f) * (ratio + 1.f));
                p2 = (cg0 <= r1) ? __expf(nsK * __logf(arg)) : 0.f;
            }
            {
                float ratio = fmaxf(-(sacc[nb][3] - qt1 * ktc1) * rKa, 1.0f + 1e-7f);
                float arg = ratio + sqrtf((ratio - 1.f) * (ratio + 1.f));
                p3 = (cg1 <= r1) ? __expf(nsK * __logf(arg)) : 0.f;
            }
            ssum0 += p0 + p1;  o00 += p0 * v0c0 + p1 * v0c1;
            ssum1 += p2 + p3;  o01 += p2 * v0c0 + p3 * v0c1;
            __half2 h01 = __floats2half2_rn(p0 * PSCALE, p1 * PSCALE);
            __half2 h23 = __floats2half2_rn(p2 * PSCALE, p3 * PSCALE);
            ap[nb][0] = *(uint32_t*)&h01;
            ap[nb][1] = *(uint32_t*)&h23;
        }

        #pragma unroll
        for (int ks = 0; ks < 2; ++ks) {
            uint32_t A[4] = { ap[2*ks][0], ap[2*ks][1], ap[2*ks+1][0], ap[2*ks+1][1] };
            uint32_t vofs = ks * (16 * KVSTR * 2);
            #pragma unroll
            for (int j = 0; j < 4; ++j) {
                uint32_t f0, f1, f2, f3;
                ldsm_x4_t(f0, f1, f2, f3, aoffV[j] + vofs);
                uint32_t B0[2] = { f0, f1 };
                uint32_t B1[2] = { f2, f3 };
                mma_f16(oacc[2*j],     A, B0);
                mma_f16(oacc[2*j + 1], A, B1);
            }
        }
    }

    #pragma unroll
    for (int m = 1; m < 4; m <<= 1) {
        ssum0 += __shfl_xor_sync(0xffffffffu, ssum0, m);
        ssum1 += __shfl_xor_sync(0xffffffffu, ssum1, m);
        o00   += __shfl_xor_sync(0xffffffffu, o00, m);
        o01   += __shfl_xor_sync(0xffffffffu, o01, m);
    }
    float rs0 = 1.0f / ssum0, rs1 = 1.0f / ssum1;
    float on0 = o00 * rs0, on1 = o01 * rs1;
    float rso0 = rs0 * RPSCALE, rso1 = rs1 * RPSCALE;
    float s20 = 0.f, s21 = 0.f;
    #pragma unroll
    for (int nb = 0; nb < 8; ++nb) {
        float a0 = oacc[nb][0] * rso0, a1 = oacc[nb][1] * rso0;
        float a2 = oacc[nb][2] * rso1, a3 = oacc[nb][3] * rso1;
        oacc[nb][0] = a0; oacc[nb][1] = a1; oacc[nb][2] = a2; oacc[nb][3] = a3;
        s20 += a0 * a0 + a1 * a1;
        s21 += a2 * a2 + a3 * a3;
    }
    #pragma unroll
    for (int m = 1; m < 4; m <<= 1) {
        s20 += __shfl_xor_sync(0xffffffffu, s20, m);
        s21 += __shfl_xor_sync(0xffffffffu, s21, m);
    }
    float hn0 = sqrtf(fmaxf(on0 * on0 - s20, 1e-12f));
    float hn1 = sqrtf(fmaxf(on1 * on1 - s21, 1e-12f));
    float sc0 = sK / hn0, sc1 = sK / hn1;

    __half* base0 = g_o + ((size_t)(b * T_ + r0)) * KP1 + h * 65;
    __half* base1 = g_o + ((size_t)(b * T_ + r1)) * KP1 + h * 65;
    if (tig == 0) {
        base0[0] = __float2half_rn(on0 * sc0);
        base1[0] = __float2half_rn(on1 * sc1);
    }
    #pragma unroll
    for (int nb = 0; nb < 8; ++nb) {
        int c = nb * 8 + 2 * tig;
        base0[1 + c]     = __float2half_rn(oacc[nb][0] * sc0);
        base0[1 + c + 1] = __float2half_rn(oacc[nb][1] * sc0);
        base1[1 + c]     = __float2half_rn(oacc[nb][2] * sc1);
        base1[1 + c + 1] = __float2half_rn(oacc[nb][3] * sc1);
    }
    if (h == 15) {
        __half* pr0 = g_o + ((size_t)(b * T_ + r0)) * KP1;
        __half* pr1 = g_o + ((size_t)(b * T_ + r1)) * KP1;
        #pragma unroll
        for (int i = 0; i < 4; ++i) {
            pr0[1040 + tig * 4 + i] = __float2half_rn(0.f);
            pr1[1040 + tig * 4 + i] = __float2half_rn(0.f);
        }
    }
}

// ---------------- kernel 6: LN + project of y1 -> l2 --------------------------
__global__ void resid_ln_project_kernel(const float* __restrict__ lnw,
                                        const float* __restrict__ lnb,
                                        const float* __restrict__ bc) {
    int row = blockIdx.x;
    int tid = threadIdx.x;
    const float* yr = g_y1 + (size_t)row * E_;
    __shared__ float red[32];
    float loc[4];
    float s = 0.f;
    #pragma unroll
    for (int u = 0; u < 4; ++u) {
        loc[u] = yr[tid + u * 256];
        s += loc[u];
    }
    float mean = block_reduce_sum(s, red) * (1.0f / E_);
    float vs = 0.f;
    #pragma unroll
    for (int u = 0; u < 4; ++u) { float d = loc[u] - mean; vs += d * d; }
    float var = block_reduce_sum(vs, red) * (1.0f / E_);
    float rstd = rsqrtf(var + 1e-5f);
    float Kb = expf(bc[0]);
    float ss = 0.f;
    __half* orow = g_l2 + (size_t)row * KP1;
    #pragma unroll
    for (int u = 0; u < 4; ++u) {
        int c = tid + u * 256;
        float y = (loc[u] - mean) * rstd * lnw[c] + lnb[c];
        orow[1 + c] = __float2half_rn(y);
        ss += y * y;
    }
    float sst = block_reduce_sum(ss, red);
    if (tid == 0) orow[0] = __float2half_rn(sqrtf(Kb + sst));
    if (tid < 31) orow[1025 + tid] = __float2half_rn(0.f);
}

// ---------------- kernel 8: hp row norm (reads fused-gelu half output) -------
__global__ void hp_norm_kernel(const float* __restrict__ mc) {
    int row = blockIdx.x;
    int tid = threadIdx.x;
    __half* op = g_hp + (size_t)row * KP4;
    __shared__ float red[32];
    float Km = expf(mc[0]);
    float ss = 0.f;
    for (int c = tid; c < MEXP; c += 256) {
        float g = __half2float(op[1 + c]);
        ss += g * g;
    }
    float sst = block_reduce_sum(ss, red);
    if (tid == 0) op[0] = __float2half_rn(sqrtf(Km + sst));
    if (tid < 28) op[4100 + tid] = __float2half_rn(0.f);
}

// ---------------- kernel 10: final norm column (out[.,1..] already written) --
__global__ void final_norm_kernel(const float* __restrict__ bc,
                                  float* __restrict__ out) {
    int row = blockIdx.x;
    int tid = threadIdx.x;
    float* orow = out + (size_t)row * (E_ + 1);
    __shared__ float red[32];
    float Kb = expf(bc[0]);
    float ss = 0.f;
    #pragma unroll
    for (int u = 0; u < 4; ++u) {
        float y = orow[1 + tid + u * 256];
        ss += y * y;
    }
    float sst = block_reduce_sum(ss, red);
    if (tid == 0) orow[0] = sqrtf(Kb + sst);
}

// ---------------- launch -----------------------------------------------------
extern "C" void kernel_launch(void* const* d_in, const int* in_sizes, int n_in,
                              void* d_out, int out_size) {
    const float* x      = (const float*)d_in[0];
    const float* bc     = (const float*)d_in[1];
    const float* mc     = (const float*)d_in[2];
    const float* acurv  = (const float*)d_in[3];
    const float* w_qkv  = (const float*)d_in[4];
    const float* w_ap   = (const float*)d_in[5];
    const float* b_ap   = (const float*)d_in[6];
    const float* w_me   = (const float*)d_in[7];
    const float* b_me   = (const float*)d_in[8];
    const float* w_ms   = (const float*)d_in[9];
    const float* b_ms   = (const float*)d_in[10];
    const float* lnw    = (const float*)d_in[11];
    const float* lnb    = (const float*)d_in[12];
    float* out = (float*)d_out;

    __half *p_l1, *p_qkv, *p_o, *p_l2, *p_hp, *p_wq, *p_wa, *p_we, *p_ws;
    float  *p_y1;
    cudaGetSymbolAddress((void**)&p_l1,  g_l1);
    cudaGetSymbolAddress((void**)&p_qkv, g_qkv);
    cudaGetSymbolAddress((void**)&p_o,   g_o);
    cudaGetSymbolAddress((void**)&p_y1,  g_y1);
    cudaGetSymbolAddress((void**)&p_l2,  g_l2);
    cudaGetSymbolAddress((void**)&p_hp,  g_hp);
    cudaGetSymbolAddress((void**)&p_wq,  g_wt_qkv);
    cudaGetSymbolAddress((void**)&p_wa,  g_wt_ap);
    cudaGetSymbolAddress((void**)&p_we,  g_wt_me);
    cudaGetSymbolAddress((void**)&p_ws,  g_wt_ms);

    const int GSMEM = 4 * HBYTES;   // 40960 bytes
    cudaFuncSetAttribute(gemm_f16_kernel,
                         cudaFuncAttributeMaxDynamicSharedMemorySize, GSMEM);

    transpose_all_kernel<<<TC0 + TC1 + TC2 + TC3, dim3(32, 8)>>>(
        w_qkv, w_ap, w_me, w_ms);

    ln_project_kernel<<<MROWS, 256>>>(x, lnw, lnb, bc, p_l1);
    // qkv = l1 @ Wqkv (half out)
    gemm_f16_kernel<<<dim3(QKVN/128, MROWS/128), 256, GSMEM>>>(
        p_l1, KP1, p_wq, KP1, nullptr, p_qkv, QKVN, QKVN, KP1/32, 2, nullptr);
    rope_prep_kernel<<<(B_ * H_ * T_) / 8, 256>>>(acurv);
    attn_kernel<<<dim3(T_ / 128, B_ * H_), 256>>>(acurv);
    // y1 = o @ Wap + b_ap + x  (fp32, fused residual)
    gemm_f16_kernel<<<dim3(E_/128, MROWS/128), 256, GSMEM>>>(
        p_o, KP1, p_wa, KP1, b_ap, p_y1, E_, E_, KP1/32, 3, x);
    resid_ln_project_kernel<<<MROWS, 256>>>(lnw, lnb, bc);
    // hp[.,1+c] = gelu(l2 @ Wme + b_me)  (half, fused gelu)
    gemm_f16_kernel<<<dim3(NP_ME/128, MROWS/128), 256, GSMEM>>>(
        p_l2, KP1, p_we, KP1, b_me, p_hp, KP4, MEXP, KP1/32, 1, nullptr);
    hp_norm_kernel<<<MROWS, 256>>>(mc);
    // out[.,1+c] = hp @ Wms + b_ms + y1  (fp32, fused residual, strided into out)
    gemm_f16_kernel<<<dim3(E_/128, MROWS/128), 256, GSMEM>>>(
        p_hp, KP4, p_ws, KP4, b_ms, out + 1, E_ + 1, E_, KP4/32, 4, p_y1);
    final_norm_kernel<<<MROWS, 256>>>(bc, out);
}

// round 16
// speedup vs baseline: 1.4842x; 1.0204x over previous
#include <cuda_runtime.h>
#include <cuda_fp16.h>
#include <math.h>
#include <stdint.h>

// Problem dims
#define B_  2
#define T_  2048
#define E_  1024
#define H_  16
#define D_  64
#define MROWS (B_*T_)            // 4096
#define QKVN  (3*E_)             // 3072
#define MEXP  4099               // 4E+3
// padded K dims for tensor-core GEMMs (multiples of 32)
#define KP1   1056               // pads 1025 and 1040
#define KP4   4128               // pads 4100
#define NP_ME 4224               // padded N for mlp expand (4099 -> 33*128)

// ---------------- scratch (static device globals; no allocation) -------------
__device__ __half g_l1 [MROWS*KP1];
__device__ __half g_qkv[MROWS*QKVN];
__device__ __half g_Q  [B_*H_*T_*D_];
__device__ __half g_Kr [B_*H_*T_*D_];
__device__ __half g_V  [B_*H_*T_*D_];
__device__ float  g_qt [B_*H_*T_];
__device__ float  g_kt [B_*H_*T_];
__device__ float  g_v0 [B_*H_*T_];
__device__ __half g_o  [MROWS*KP1];
__device__ float  g_y1 [MROWS*E_];
__device__ __half g_l2 [MROWS*KP1];
__device__ __half g_hp [MROWS*KP4];
__device__ float  g_hpsum[MROWS];
__device__ float  g_osum [MROWS];
// transposed + fp16-rounded + zero-padded weights: Wt[N,K]
__device__ __half g_wt_qkv[QKVN*KP1];
__device__ __half g_wt_ap [E_*KP1];
__device__ __half g_wt_me [NP_ME*KP1];
__device__ __half g_wt_ms [E_*KP4];

// ---------------- helpers -----------------------------------------------------
__device__ __forceinline__ uint32_t smem_u32(const void* p) {
    uint32_t a;
    asm("{ .reg .u64 t; cvta.to.shared.u64 t, %1; cvt.u32.u64 %0, t; }" : "=r"(a) : "l"(p));
    return a;
}
#define CP_ASYNC16(dst, src) \
    asm volatile("cp.async.cg.shared.global [%0], [%1], 16;" :: "r"(dst), "l"(src))
#define CP_COMMIT()  asm volatile("cp.async.commit_group;")
#define CP_WAIT(n)   asm volatile("cp.async.wait_group %0;" :: "n"(n))

// fp16 mma, fp32 accumulate
__device__ __forceinline__ void mma_f16(float* c, const uint32_t* a, const uint32_t* b) {
    asm volatile(
        "mma.sync.aligned.m16n8k16.row.col.f32.f16.f16.f32 "
        "{%0,%1,%2,%3}, {%4,%5,%6,%7}, {%8,%9}, {%0,%1,%2,%3};"
        : "+f"(c[0]), "+f"(c[1]), "+f"(c[2]), "+f"(c[3])
        : "r"(a[0]), "r"(a[1]), "r"(a[2]), "r"(a[3]), "r"(b[0]), "r"(b[1]));
}
__device__ __forceinline__ void ldsm_x4(uint32_t& r0, uint32_t& r1,
                                        uint32_t& r2, uint32_t& r3, uint32_t addr) {
    asm volatile("ldmatrix.sync.aligned.m8n8.x4.shared.b16 {%0,%1,%2,%3}, [%4];"
        : "=r"(r0), "=r"(r1), "=r"(r2), "=r"(r3) : "r"(addr));
}
__device__ __forceinline__ void ldsm_x4_t(uint32_t& r0, uint32_t& r1,
                                          uint32_t& r2, uint32_t& r3, uint32_t addr) {
    asm volatile("ldmatrix.sync.aligned.m8n8.x4.trans.shared.b16 {%0,%1,%2,%3}, [%4];"
        : "=r"(r0), "=r"(r1), "=r"(r2), "=r"(r3) : "r"(addr));
}

__device__ __forceinline__ float block_reduce_sum(float v, float* red) {
    int tid = threadIdx.x;
    #pragma unroll
    for (int o = 16; o; o >>= 1) v += __shfl_xor_sync(0xffffffffu, v, o);
    if ((tid & 31) == 0) red[tid >> 5] = v;
    __syncthreads();
    float r = (tid < (int)(blockDim.x >> 5)) ? red[tid] : 0.f;
    if (tid < 32) {
        #pragma unroll
        for (int o = 16; o; o >>= 1) r += __shfl_xor_sync(0xffffffffu, r, o);
        if (tid == 0) red[0] = r;
    }
    __syncthreads();
    float out = red[0];
    __syncthreads();
    return out;
}

// ---------------- merged weight transpose + fp16 round + zero pad ------------
#define TC0 (33*96)     // qkv : K=1025 N=3072 Kpad=KP1
#define TC1 (33*32)     // ap  : K=1040 N=1024 Kpad=KP1
#define TC2 (33*132)    // me  : K=1025 N=4099 Kpad=KP1, Npad=4224
#define TC3 (129*32)    // ms  : K=4100 N=1024 Kpad=KP4
__global__ void transpose_all_kernel(const float* __restrict__ w_qkv,
                                     const float* __restrict__ w_ap,
                                     const float* __restrict__ w_me,
                                     const float* __restrict__ w_ms) {
    __shared__ float s[32][33];
    int id = blockIdx.x;
    const float* W; __half* Wt;
    int K, N, Kpad, nx, r;
    if (id < TC0)                  { r = id;                W = w_qkv; Wt = g_wt_qkv; K = 1025; N = 3072; Kpad = KP1; nx = 33; }
    else if (id < TC0+TC1)         { r = id - TC0;          W = w_ap;  Wt = g_wt_ap;  K = 1040; N = 1024; Kpad = KP1; nx = 33; }
    else if (id < TC0+TC1+TC2)     { r = id - TC0 - TC1;    W = w_me;  Wt = g_wt_me;  K = 1025; N = 4099; Kpad = KP1; nx = 33; }
    else                           { r = id - TC0 - TC1-TC2;W = w_ms;  Wt = g_wt_ms;  K = 4100; N = 1024; Kpad = KP4; nx = 129; }
    int k0 = (r % nx) * 32, n0 = (r / nx) * 32;
    int tx = threadIdx.x, ty = threadIdx.y;          // 32 x 8
    #pragma unroll
    for (int yy = ty; yy < 32; yy += 8) {
        int k = k0 + yy, n = n0 + tx;
        float v = (k < K && n < N) ? W[(size_t)k * N + n] : 0.f;
        s[yy][tx] = v;
    }
    __syncthreads();
    #pragma unroll
    for (int yy = ty; yy < 32; yy += 8) {
        int n = n0 + yy, k = k0 + tx;
        Wt[(size_t)n * Kpad + k] = __float2half_rn(s[tx][yy]);
    }
}

// ---------------- fp16 tensor-core GEMM (3-stage cp.async, BK=32) -------------
// modes:
//  1: C(half)[r*ldc + 1 + c] = fp16(gelu(acc+bias)); row g^2 sums -> g_hpsum
//  2: C(half)[r*ldc + c]     = fp16(acc + bias)
//  3: C(float)[r*ldc + c]    = acc + bias + X2[r*E_ + c]
//  4: mode 3 + row sums of result^2 -> g_osum
#define HSTR 40                      // halves per SMEM row (80 B) — conflict-free
#define HBUF (128*HSTR)              // halves per buffer
#define HBYTES (HBUF*2)              // bytes per buffer (10240)
__global__ void __launch_bounds__(256, 2) gemm_f16_kernel(
        const __half* __restrict__ A, int lda,
        const __half* __restrict__ Bt, int ldb,
        const float* __restrict__ bias,
        void* __restrict__ Cv, int ldc, int Nact, int nchunks, int mode,
        const float* __restrict__ X2) {
    extern __shared__ __half hsm[];
    uint32_t smaddr = smem_u32(hsm);
    int tid = threadIdx.x;
    int lane = tid & 31, w = tid >> 5;
    int grp = lane >> 2, tig = lane & 3;
    int wm = w >> 1, wn = w & 1;
    int row0 = blockIdx.y * 128, col0 = blockIdx.x * 128;

    int q8 = lane >> 3, rr = lane & 7;
    uint32_t aoffA[2], aoffB[4];
    #pragma unroll
    for (int mi = 0; mi < 2; ++mi) {
        int rowa = wm * 32 + mi * 16 + (q8 & 1) * 8 + rr;
        aoffA[mi] = smaddr + (uint32_t)rowa * (HSTR * 2) + (q8 >> 1) * 16;
    }
    #pragma unroll
    for (int j = 0; j < 4; ++j) {
        int nb = wn * 64 + j * 16 + (q8 >> 1) * 8 + rr;
        aoffB[j] = smaddr + 3 * HBYTES + (uint32_t)nb * (HSTR * 2) + (q8 & 1) * 16;
    }

    float acc[2][8][4];
    #pragma unroll
    for (int mi = 0; mi < 2; ++mi)
        #pragma unroll
        for (int ni = 0; ni < 8; ++ni)
            #pragma unroll
            for (int cc = 0; cc < 4; ++cc) acc[mi][ni][cc] = 0.f;

    const __half* Arow = A  + (size_t)row0 * lda;
    const __half* Brow = Bt + (size_t)col0 * ldb;

    auto load_chunk = [&](int buf, int kc) {
        int k0 = kc * 32;
        uint32_t abase = smaddr + buf * HBYTES;
        uint32_t bbase = smaddr + (3 + buf) * HBYTES;
        #pragma unroll
        for (int u = 0; u < 2; ++u) {
            int idx = tid + u * 256;             // 0..511
            int r = idx >> 2, c = idx & 3;       // 128 rows x 4 16B-chunks
            CP_ASYNC16(abase + r * (HSTR * 2) + c * 16,
                       Arow + (size_t)r * lda + k0 + c * 8);
            CP_ASYNC16(bbase + r * (HSTR * 2) + c * 16,
                       Brow + (size_t)r * ldb + k0 + c * 8);
        }
        CP_COMMIT();
    };

    load_chunk(0, 0);
    load_chunk(1, 1);            // all call sites have nchunks >= 2
    int bufi = 0;
    for (int i = 0; i < nchunks; ++i) {
        if (i + 2 < nchunks) {
            int nb3 = bufi + 2; if (nb3 >= 3) nb3 -= 3;
            load_chunk(nb3, i + 2);
            CP_WAIT(2);
        }
        else if (i + 1 < nchunks) { CP_WAIT(1); }
        else { CP_WAIT(0); }
        __syncthreads();
        uint32_t bufofs = bufi * HBYTES;
        #pragma unroll
        for (int ks = 0; ks < 2; ++ks) {
            uint32_t kofs = bufofs + ks * 32;
            uint32_t a[2][4];
            ldsm_x4(a[0][0], a[0][1], a[0][2], a[0][3], aoffA[0] + kofs);
            ldsm_x4(a[1][0], a[1][1], a[1][2], a[1][3], aoffA[1] + kofs);
            uint32_t b[8][2];
            #pragma unroll
            for (int j = 0; j < 4; ++j) {
                uint32_t r0, r1, r2, r3;
                ldsm_x4(r0, r1, r2, r3, aoffB[j] + kofs);
                b[2*j][0] = r0;   b[2*j][1] = r1;
                b[2*j+1][0] = r2; b[2*j+1][1] = r3;
            }
            #pragma unroll
            for (int mi = 0; mi < 2; ++mi)
                #pragma unroll
                for (int ni = 0; ni < 8; ++ni)
                    mma_f16(acc[mi][ni], a[mi], b[ni]);
        }
        __syncthreads();
        bufi = (bufi == 2) ? 0 : bufi + 1;
    }

    if (mode == 2) {
        __half* C = (__half*)Cv;
        #pragma unroll
        for (int mi = 0; mi < 2; ++mi) {
            int rbase = row0 + wm * 32 + mi * 16 + grp;
            #pragma unroll
            for (int ni = 0; ni < 8; ++ni) {
                int gc = col0 + wn * 64 + ni * 8 + tig * 2;
                if (gc < Nact) {
                    float b0 = bias ? bias[gc] : 0.f;
                    float b1 = (bias && gc + 1 < Nact) ? bias[gc + 1] : 0.f;
                    __half* p0 = C + (size_t)rbase * ldc + gc;
                    __half* p1 = C + (size_t)(rbase + 8) * ldc + gc;
                    p0[0] = __float2half_rn(acc[mi][ni][0] + b0);
                    if (gc + 1 < Nact) p0[1] = __float2half_rn(acc[mi][ni][1] + b1);
                    p1[0] = __float2half_rn(acc[mi][ni][2] + b0);
                    if (gc + 1 < Nact) p1[1] = __float2half_rn(acc[mi][ni][3] + b1);
                }
            }
        }
    } else if (mode == 1) {
        __half* C = (__half*)Cv;
        float rsum[2][2] = {{0.f, 0.f}, {0.f, 0.f}};
        #pragma unroll
        for (int mi = 0; mi < 2; ++mi) {
            int rbase = row0 + wm * 32 + mi * 16 + grp;
            #pragma unroll
            for (int ni = 0; ni < 8; ++ni) {
                int gc = col0 + wn * 64 + ni * 8 + tig * 2;
                if (gc < Nact) {
                    float b0 = bias ? bias[gc] : 0.f;
                    float b1 = (bias && gc + 1 < Nact) ? bias[gc + 1] : 0.f;
                    float v0 = acc[mi][ni][0] + b0;
                    float v1 = acc[mi][ni][1] + b1;
                    float v2 = acc[mi][ni][2] + b0;
                    float v3 = acc[mi][ni][3] + b1;
                    float g0 = 0.5f * v0 * (1.0f + erff(v0 * 0.70710678118654752f));
                    float g1 = 0.5f * v1 * (1.0f + erff(v1 * 0.70710678118654752f));
                    float g2 = 0.5f * v2 * (1.0f + erff(v2 * 0.70710678118654752f));
                    float g3 = 0.5f * v3 * (1.0f + erff(v3 * 0.70710678118654752f));
                    __half* p0 = C + (size_t)rbase * ldc + 1 + gc;
                    __half* p1 = C + (size_t)(rbase + 8) * ldc + 1 + gc;
                    p0[0] = __float2half_rn(g0);
                    rsum[mi][0] += g0 * g0;
                    rsum[mi][1] += g2 * g2;
                    if (gc + 1 < Nact) {
                        p0[1] = __float2half_rn(g1);
                        rsum[mi][0] += g1 * g1;
                        rsum[mi][1] += g3 * g3;
                    }
                    p1[0] = __float2half_rn(g2);
                    if (gc + 1 < Nact) p1[1] = __float2half_rn(g3);
                }
            }
        }
        #pragma unroll
        for (int m = 1; m < 4; m <<= 1) {
            rsum[0][0] += __shfl_xor_sync(0xffffffffu, rsum[0][0], m);
            rsum[0][1] += __shfl_xor_sync(0xffffffffu, rsum[0][1], m);
            rsum[1][0] += __shfl_xor_sync(0xffffffffu, rsum[1][0], m);
            rsum[1][1] += __shfl_xor_sync(0xffffffffu, rsum[1][1], m);
        }
        if (tig == 0) {
            #pragma unroll
            for (int mi = 0; mi < 2; ++mi) {
                int rbase = row0 + wm * 32 + mi * 16 + grp;
                atomicAdd(&g_hpsum[rbase], rsum[mi][0]);
                atomicAdd(&g_hpsum[rbase + 8], rsum[mi][1]);
            }
        }
    } else {   // modes 3/4: fp32 out with fused residual add (X2 stride E_)
        float* C = (float*)Cv;
        float rsum[2][2] = {{0.f, 0.f}, {0.f, 0.f}};
        #pragma unroll
        for (int mi = 0; mi < 2; ++mi) {
            int rbase = row0 + wm * 32 + mi * 16 + grp;
            #pragma unroll
            for (int ni = 0; ni < 8; ++ni) {
                int gc = col0 + wn * 64 + ni * 8 + tig * 2;
                if (gc < Nact) {
                    float b0 = bias ? bias[gc] : 0.f;
                    float b1 = (bias && gc + 1 < Nact) ? bias[gc + 1] : 0.f;
                    const float* x0 = X2 + (size_t)rbase * E_ + gc;
                    const float* x1 = X2 + (size_t)(rbase + 8) * E_ + gc;
                    float* p0 = C + (size_t)rbase * ldc + gc;
                    float* p1 = C + (size_t)(rbase + 8) * ldc + gc;
                    float y0 = acc[mi][ni][0] + b0 + x0[0];
                    float y2 = acc[mi][ni][2] + b0 + x1[0];
                    p0[0] = y0;
                    p1[0] = y2;
                    rsum[mi][0] += y0 * y0;
                    rsum[mi][1] += y2 * y2;
                    if (gc + 1 < Nact) {
                        float y1v = acc[mi][ni][1] + b1 + x0[1];
                        float y3v = acc[mi][ni][3] + b1 + x1[1];
                        p0[1] = y1v;
                        p1[1] = y3v;
                        rsum[mi][0] += y1v * y1v;
                        rsum[mi][1] += y3v * y3v;
                    }
                }
            }
        }
        if (mode == 4) {
            #pragma unroll
            for (int m = 1; m < 4; m <<= 1) {
                rsum[0][0] += __shfl_xor_sync(0xffffffffu, rsum[0][0], m);
                rsum[0][1] += __shfl_xor_sync(0xffffffffu, rsum[0][1], m);
                rsum[1][0] += __shfl_xor_sync(0xffffffffu, rsum[1][0], m);
                rsum[1][1] += __shfl_xor_sync(0xffffffffu, rsum[1][1], m);
            }
            if (tig == 0) {
                #pragma unroll
                for (int mi = 0; mi < 2; ++mi) {
                    int rbase = row0 + wm * 32 + mi * 16 + grp;
                    atomicAdd(&g_osum[rbase], rsum[mi][0]);
                    atomicAdd(&g_osum[rbase + 8], rsum[mi][1]);
                }
            }
        }
    }
}

// ---------------- kernel 1: LN + project of x -> l1 (M, KP1) half -------------
__global__ void ln_project_kernel(const float* __restrict__ x,
                                  const float* __restrict__ lnw,
                                  const float* __restrict__ lnb,
                                  const float* __restrict__ bc,
                                  __half* __restrict__ out) {
    int row = blockIdx.x;
    int tid = threadIdx.x;
    const float* xr = x + (size_t)row * E_;
    __shared__ float red[32];
    float loc[4];
    float s = 0.f;
    #pragma unroll
    for (int u = 0; u < 4; ++u) { loc[u] = xr[tid + u * 256]; s += loc[u]; }
    float mean = block_reduce_sum(s, red) * (1.0f / E_);
    float vs = 0.f;
    #pragma unroll
    for (int u = 0; u < 4; ++u) { float d = loc[u] - mean; vs += d * d; }
    float var = block_reduce_sum(vs, red) * (1.0f / E_);
    float rstd = rsqrtf(var + 1e-5f);
    float Kb = expf(bc[0]);
    float ss = 0.f;
    __half* orow = out + (size_t)row * KP1;
    #pragma unroll
    for (int u = 0; u < 4; ++u) {
        int c = tid + u * 256;
        float y = (loc[u] - mean) * rstd * lnw[c] + lnb[c];
        orow[1 + c] = __float2half_rn(y);
        ss += y * y;
    }
    float sst = block_reduce_sum(ss, red);
    if (tid == 0) orow[0] = __float2half_rn(sqrtf(Kb + sst));
    if (tid < 31) orow[1025 + tid] = __float2half_rn(0.f);
}

// ---------------- kernel 3: RoPE + per-head norms (fp16 Q/K/V) ---------------
__global__ void rope_prep_kernel(const float* __restrict__ curv) {
    int tid = threadIdx.x;
    int lane = tid & 31;
    int rsub = tid >> 5;
    int r = blockIdx.x * 8 + rsub;            // r = bh*T + t
    int bh = r >> 11;
    int t  = r & (T_ - 1);
    int b  = bh >> 4;
    int h  = bh & 15;
    float Ka = expf(curv[h]);
    size_t base = ((size_t)(b * T_ + t)) * QKVN + h * D_;
    float q1 = __half2float(g_qkv[base + lane]);
    float q2 = __half2float(g_qkv[base + 32 + lane]);
    float k1 = __half2float(g_qkv[base + E_ + lane]);
    float k2 = __half2float(g_qkv[base + E_ + 32 + lane]);
    float v1 = __half2float(g_qkv[base + 2*E_ + lane]);
    float v2 = __half2float(g_qkv[base + 2*E_ + 32 + lane]);
    float inv = powf(10000.0f, -(float)lane * (1.0f / 32.0f));
    float fr = (float)t * inv;
    float sn, cs;
    sincosf(fr, &sn, &cs);
    __half qah = __float2half_rn(q1 * cs + q2 * sn);
    __half qbh = __float2half_rn(-q1 * sn + q2 * cs);
    __half kah = __float2half_rn(k1 * cs + k2 * sn);
    __half kbh = __float2half_rn(-k1 * sn + k2 * cs);
    float qa = __half2float(qah), qb = __half2float(qbh);
    float ka = __half2float(kah), kb = __half2float(kbh);
    float sq = qa * qa + qb * qb;
    float sk = ka * ka + kb * kb;
    float sv = v1 * v1 + v2 * v2;
    #pragma unroll
    for (int o = 16; o; o >>= 1) {
        sq += __shfl_xor_sync(0xffffffffu, sq, o);
        sk += __shfl_xor_sync(0xffffffffu, sk, o);
        sv += __shfl_xor_sync(0xffffffffu, sv, o);
    }
    size_t ob = ((size_t)bh * T_ + t) * D_;
    g_Q[ob + lane] = qah;  g_Q[ob + 32 + lane] = qbh;
    g_Kr[ob + lane] = kah; g_Kr[ob + 32 + lane] = kbh;
    g_V[ob + lane] = __float2half_rn(v1);
    g_V[ob + 32 + lane] = __float2half_rn(v2);
    if (lane == 0) {
        g_qt[r] = sqrtf(Ka + sq);
        g_kt[r] = sqrtf(Ka + sk);
        g_v0[r] = sqrtf(Ka + sv);
    }
}

// ---------------- kernel 4: hyperbolic causal attention (all-fp16 mma) -------
#define KVSTR 72                 // halves per K/V smem row (144 B, D=64 + pad)
#define PSCALE 1024.0f
#define RPSCALE (1.0f/1024.0f)
__global__ void __launch_bounds__(256, 2) attn_kernel(const float* __restrict__ curv) {
    __shared__ __align__(16) __half ksh[32 * KVSTR];
    __shared__ __align__(16) __half vsh[32 * KVSTR];
    __shared__ float kts[32], v0s[32];

    int bh = blockIdx.y;
    int b = bh >> 4, h = bh & 15;
    int q0 = blockIdx.x * 128;
    int tid = threadIdx.x, lane = tid & 31, w = tid >> 5;
    int grp = lane >> 2, tig = lane & 3;
    float Ka = expf(curv[h]);
    float sK = sqrtf(Ka);
    float rKa = 1.0f / Ka;
    float nsK = -sK;

    int r0 = q0 + w * 16 + grp;
    int r1 = r0 + 8;

    uint32_t kshaddr = smem_u32(ksh);
    uint32_t vshaddr = smem_u32(vsh);
    int q8 = lane >> 3, rr = lane & 7;
    uint32_t aoffK[2];
    #pragma unroll
    for (int j = 0; j < 2; ++j) {
        int nb = j * 16 + (q8 >> 1) * 8 + rr;
        aoffK[j] = kshaddr + (uint32_t)nb * (KVSTR * 2) + (q8 & 1) * 16;
    }
    uint32_t aoffV[4];
    {
        int krow = (q8 & 1) * 8 + rr;
        int ncol = (q8 >> 1) * 8;
        #pragma unroll
        for (int j = 0; j < 4; ++j)
            aoffV[j] = vshaddr + (uint32_t)(krow * KVSTR + j * 16 + ncol) * 2;
    }

    uint32_t qh[4][4];
    {
        const __half* Q0 = g_Q + ((size_t)bh * T_ + r0) * D_;
        const __half* Q1 = g_Q + ((size_t)bh * T_ + r1) * D_;
        #pragma unroll
        for (int ks = 0; ks < 4; ++ks) {
            qh[ks][0] = *(const uint32_t*)(Q0 + ks * 16 + 2 * tig);
            qh[ks][1] = *(const uint32_t*)(Q1 + ks * 16 + 2 * tig);
            qh[ks][2] = *(const uint32_t*)(Q0 + ks * 16 + 8 + 2 * tig);
            qh[ks][3] = *(const uint32_t*)(Q1 + ks * 16 + 8 + 2 * tig);
        }
    }
    float qt0 = g_qt[(size_t)bh * T_ + r0];
    float qt1 = g_qt[(size_t)bh * T_ + r1];

    float oacc[8][4];
    #pragma unroll
    for (int nb = 0; nb < 8; ++nb)
        #pragma unroll
        for (int cc = 0; cc < 4; ++cc) oacc[nb][cc] = 0.f;
    float ssum0 = 0.f, ssum1 = 0.f, o00 = 0.f, o01 = 0.f;

    for (int k0 = 0; k0 < q0 + 128; k0 += 32) {
        __syncthreads();
        {
            int rr2 = tid >> 3, c = tid & 7;
            *(uint4*)&ksh[rr2 * KVSTR + c * 8] =
                *(const uint4*)(g_Kr + ((size_t)bh * T_ + k0 + rr2) * D_ + c * 8);
            *(uint4*)&vsh[rr2 * KVSTR + c * 8] =
                *(const uint4*)(g_V + ((size_t)bh * T_ + k0 + rr2) * D_ + c * 8);
        }
        if (tid < 32) {
            kts[tid] = g_kt[(size_t)bh * T_ + k0 + tid];
            v0s[tid] = g_v0[(size_t)bh * T_ + k0 + tid];
        }
        __syncthreads();
        if (q0 + w * 16 + 15 < k0) continue;

        float sacc[4][4];
        #pragma unroll
        for (int nb = 0; nb < 4; ++nb)
            #pragma unroll
            for (int cc = 0; cc < 4; ++cc) sacc[nb][cc] = 0.f;
        #pragma unroll
        for (int ks = 0; ks < 4; ++ks) {
            uint32_t kofs = ks * 32;
            uint32_t bb[4][2];
            #pragma unroll
            for (int j = 0; j < 2; ++j) {
                uint32_t f0, f1, f2, f3;
                ldsm_x4(f0, f1, f2, f3, aoffK[j] + kofs);
                bb[2*j][0] = f0;   bb[2*j][1] = f1;
                bb[2*j+1][0] = f2; bb[2*j+1][1] = f3;
            }
            #pragma unroll
            for (int nb = 0; nb < 4; ++nb)
                mma_f16(sacc[nb], qh[ks], bb[nb]);
        }

        uint32_t ap[4][2];
        #pragma unroll
        for (int nb = 0; nb < 4; ++nb) {
            int cl = nb * 8 + 2 * tig;
            float ktc0 = kts[cl], ktc1 = kts[cl + 1];
            float v0c0 = v0s[cl], v0c1 = v0s[cl + 1];
            int cg0 = k0 + cl, cg1 = cg0 + 1;
            float p0, p1, p2, p3;
            {
                float ratio = fmaxf(-(sacc[nb][0] - qt0 * ktc0) * rKa, 1.0f + 1e-7f);
                float arg = ratio + sqrtf((ratio - 1.f) * (ratio + 1.f));
                p0 = (cg0 <= r0) ? __expf(nsK * __logf(arg)) : 0.f;
            }
            {
                float ratio = fmaxf(-(sacc[nb][1] - qt0 * ktc1) * rKa, 1.0f + 1e-7f);
                float arg = ratio + sqrtf((ratio - 1.f) * (ratio + 1.f));
                p1 = (cg1 <= r0) ? __expf(nsK * __logf(arg)) : 0.f;
            }
            {
                float ratio = fmaxf(-(sacc[nb][2] - qt1 * ktc0) * rKa, 1.0f + 1e-7f);
                float arg = ratio + sqrtf((ratio - 1.f) * (ratio + 1.f));
                p2 = (cg0 <= r1) ? __expf(nsK * __logf(arg)) : 0.f;
            }
            {
                float ratio = fmaxf(-(sacc[nb][3] - qt1 * ktc1) * rKa, 1.0f + 1e-7f);
                float arg = ratio + sqrtf((ratio - 1.f) * (ratio + 1.f));
                p3 = (cg1 <= r1) ? __expf(nsK * __logf(arg)) : 0.f;
            }
            ssum0 += p0 + p1;  o00 += p0 * v0c0 + p1 * v0c1;
            ssum1 += p2 + p3;  o01 += p2 * v0c0 + p3 * v0c1;
            __half2 h01 = __floats2half2_rn(p0 * PSCALE, p1 * PSCALE);
            __half2 h23 = __floats2half2_rn(p2 * PSCALE, p3 * PSCALE);
            ap[nb][0] = *(uint32_t*)&h01;
            ap[nb][1] = *(uint32_t*)&h23;
        }

        #pragma unroll
        for (int ks = 0; ks < 2; ++ks) {
            uint32_t A[4] = { ap[2*ks][0], ap[2*ks][1], ap[2*ks+1][0], ap[2*ks+1][1] };
            uint32_t vofs = ks * (16 * KVSTR * 2);
            #pragma unroll
            for (int j = 0; j < 4; ++j) {
                uint32_t f0, f1, f2, f3;
                ldsm_x4_t(f0, f1, f2, f3, aoffV[j] + vofs);
                uint32_t B0[2] = { f0, f1 };
                uint32_t B1[2] = { f2, f3 };
                mma_f16(oacc[2*j],     A, B0);
                mma_f16(oacc[2*j + 1], A, B1);
            }
        }
    }

    #pragma unroll
    for (int m = 1; m < 4; m <<= 1) {
        ssum0 += __shfl_xor_sync(0xffffffffu, ssum0, m);
        ssum1 += __shfl_xor_sync(0xffffffffu, ssum1, m);
        o00   += __shfl_xor_sync(0xffffffffu, o00, m);
        o01   += __shfl_xor_sync(0xffffffffu, o01, m);
    }
    float rs0 = 1.0f / ssum0, rs1 = 1.0f / ssum1;
    float on0 = o00 * rs0, on1 = o01 * rs1;
    float rso0 = rs0 * RPSCALE, rso1 = rs1 * RPSCALE;
    float s20 = 0.f, s21 = 0.f;
    #pragma unroll
    for (int nb = 0; nb < 8; ++nb) {
        float a0 = oacc[nb][0] * rso0, a1 = oacc[nb][1] * rso0;
        float a2 = oacc[nb][2] * rso1, a3 = oacc[nb][3] * rso1;
        oacc[nb][0] = a0; oacc[nb][1] = a1; oacc[nb][2] = a2; oacc[nb][3] = a3;
        s20 += a0 * a0 + a1 * a1;
        s21 += a2 * a2 + a3 * a3;
    }
    #pragma unroll
    for (int m = 1; m < 4; m <<= 1) {
        s20 += __shfl_xor_sync(0xffffffffu, s20, m);
        s21 += __shfl_xor_sync(0xffffffffu, s21, m);
    }
    float hn0 = sqrtf(fmaxf(on0 * on0 - s20, 1e-12f));
    float hn1 = sqrtf(fmaxf(on1 * on1 - s21, 1e-12f));
    float sc0 = sK / hn0, sc1 = sK / hn1;

    __half* base0 = g_o + ((size_t)(b * T_ + r0)) * KP1 + h * 65;
    __half* base1 = g_o + ((size_t)(b * T_ + r1)) * KP1 + h * 65;
    if (tig == 0) {
        base0[0] = __float2half_rn(on0 * sc0);
        base1[0] = __float2half_rn(on1 * sc1);
    }
    #pragma unroll
    for (int nb = 0; nb < 8; ++nb) {
        int c = nb * 8 + 2 * tig;
        base0[1 + c]     = __float2half_rn(oacc[nb][0] * sc0);
        base0[1 + c + 1] = __float2half_rn(oacc[nb][1] * sc0);
        base1[1 + c]     = __float2half_rn(oacc[nb][2] * sc1);
        base1[1 + c + 1] = __float2half_rn(oacc[nb][3] * sc1);
    }
    if (h == 15) {
        __half* pr0 = g_o + ((size_t)(b * T_ + r0)) * KP1;
        __half* pr1 = g_o + ((size_t)(b * T_ + r1)) * KP1;
        #pragma unroll
        for (int i = 0; i < 4; ++i) {
            pr0[1040 + tig * 4 + i] = __float2half_rn(0.f);
            pr1[1040 + tig * 4 + i] = __float2half_rn(0.f);
        }
    }
}

// ---------------- kernel 6: LN + project of y1 -> l2 (also zeroes g_hpsum) ---
__global__ void resid_ln_project_kernel(const float* __restrict__ lnw,
                                        const float* __restrict__ lnb,
                                        const float* __restrict__ bc) {
    int row = blockIdx.x;
    int tid = threadIdx.x;
    const float* yr = g_y1 + (size_t)row * E_;
    __shared__ float red[32];
    float loc[4];
    float s = 0.f;
    #pragma unroll
    for (int u = 0; u < 4; ++u) {
        loc[u] = yr[tid + u * 256];
        s += loc[u];
    }
    float mean = block_reduce_sum(s, red) * (1.0f / E_);
    float vs = 0.f;
    #pragma unroll
    for (int u = 0; u < 4; ++u) { float d = loc[u] - mean; vs += d * d; }
    float var = block_reduce_sum(vs, red) * (1.0f / E_);
    float rstd = rsqrtf(var + 1e-5f);
    float Kb = expf(bc[0]);
    float ss = 0.f;
    __half* orow = g_l2 + (size_t)row * KP1;
    #pragma unroll
    for (int u = 0; u < 4; ++u) {
        int c = tid + u * 256;
        float y = (loc[u] - mean) * rstd * lnw[c] + lnb[c];
        orow[1 + c] = __float2half_rn(y);
        ss += y * y;
    }
    float sst = block_reduce_sum(ss, red);
    if (tid == 0) {
        orow[0] = __float2half_rn(sqrtf(Kb + sst));
        g_hpsum[row] = 0.f;
    }
    if (tid < 31) orow[1025 + tid] = __float2half_rn(0.f);
}

// ---------------- kernel 8: hp norm finalize (+ zero g_osum, pad) ------------
__global__ void hp_finalize_kernel(const float* __restrict__ mc) {
    int row = blockIdx.x;
    int tid = threadIdx.x;        // 32 threads
    __half* op = g_hp + (size_t)row * KP4;
    if (tid == 0) {
        op[0] = __float2half_rn(sqrtf(expf(mc[0]) + g_hpsum[row]));
        g_osum[row] = 0.f;
    }
    if (tid < 28) op[4100 + tid] = __float2half_rn(0.f);
}

// ---------------- kernel 10: final norm column from fused sums ----------------
__global__ void final_finalize_kernel(const float* __restrict__ bc,
                                      float* __restrict__ out) {
    int idx = blockIdx.x * 256 + threadIdx.x;
    float Kb = expf(bc[0]);
    out[(size_t)idx * (E_ + 1)] = sqrtf(Kb + g_osum[idx]);
}

// ---------------- launch -----------------------------------------------------
extern "C" void kernel_launch(void* const* d_in, const int* in_sizes, int n_in,
                              void* d_out, int out_size) {
    const float* x      = (const float*)d_in[0];
    const float* bc     = (const float*)d_in[1];
    const float* mc     = (const float*)d_in[2];
    const float* acurv  = (const float*)d_in[3];
    const float* w_qkv  = (const float*)d_in[4];
    const float* w_ap   = (const float*)d_in[5];
    const float* b_ap   = (const float*)d_in[6];
    const float* w_me   = (const float*)d_in[7];
    const float* b_me   = (const float*)d_in[8];
    const float* w_ms   = (const float*)d_in[9];
    const float* b_ms   = (const float*)d_in[10];
    const float* lnw    = (const float*)d_in[11];
    const float* lnb    = (const float*)d_in[12];
    float* out = (float*)d_out;

    __half *p_l1, *p_qkv, *p_o, *p_l2, *p_hp, *p_wq, *p_wa, *p_we, *p_ws;
    float  *p_y1;
    cudaGetSymbolAddress((void**)&p_l1,  g_l1);
    cudaGetSymbolAddress((void**)&p_qkv, g_qkv);
    cudaGetSymbolAddress((void**)&p_o,   g_o);
    cudaGetSymbolAddress((void**)&p_y1,  g_y1);
    cudaGetSymbolAddress((void**)&p_l2,  g_l2);
    cudaGetSymbolAddress((void**)&p_hp,  g_hp);
    cudaGetSymbolAddress((void**)&p_wq,  g_wt_qkv);
    cudaGetSymbolAddress((void**)&p_wa,  g_wt_ap);
    cudaGetSymbolAddress((void**)&p_we,  g_wt_me);
    cudaGetSymbolAddress((void**)&p_ws,  g_wt_ms);

    const int GSMEM = 6 * HBYTES;   // 61440 bytes (3-stage A + 3-stage B)
    cudaFuncSetAttribute(gemm_f16_kernel,
                         cudaFuncAttributeMaxDynamicSharedMemorySize, GSMEM);

    transpose_all_kernel<<<TC0 + TC1 + TC2 + TC3, dim3(32, 8)>>>(
        w_qkv, w_ap, w_me, w_ms);

    ln_project_kernel<<<MROWS, 256>>>(x, lnw, lnb, bc, p_l1);
    // qkv = l1 @ Wqkv (half out)
    gemm_f16_kernel<<<dim3(QKVN/128, MROWS/128), 256, GSMEM>>>(
        p_l1, KP1, p_wq, KP1, nullptr, p_qkv, QKVN, QKVN, KP1/32, 2, nullptr);
    rope_prep_kernel<<<(B_ * H_ * T_) / 8, 256>>>(acurv);
    attn_kernel<<<dim3(T_ / 128, B_ * H_), 256>>>(acurv);
    // y1 = o @ Wap + b_ap + x  (fp32, fused residual)
    gemm_f16_kernel<<<dim3(E_/128, MROWS/128), 256, GSMEM>>>(
        p_o, KP1, p_wa, KP1, b_ap, p_y1, E_, E_, KP1/32, 3, x);
    resid_ln_project_kernel<<<MROWS, 256>>>(lnw, lnb, bc);
    // hp[.,1+c] = gelu(l2 @ Wme + b_me); row sums -> g_hpsum
    gemm_f16_kernel<<<dim3(NP_ME/128, MROWS/128), 256, GSMEM>>>(
        p_l2, KP1, p_we, KP1, b_me, p_hp, KP4, MEXP, KP1/32, 1, nullptr);
    hp_finalize_kernel<<<MROWS, 32>>>(mc);
    // out[.,1+c] = hp @ Wms + b_ms + y1; row sums -> g_osum
    gemm_f16_kernel<<<dim3(E_/128, MROWS/128), 256, GSMEM>>>(
        p_hp, KP4, p_ws, KP4, b_ms, out + 1, E_ + 1, E_, KP4/32, 4, p_y1);
    final_finalize_kernel<<<MROWS/256, 256>>>(bc, out);
}

// round 17
// speedup vs baseline: 1.4945x; 1.0070x over previous
#include <cuda_runtime.h>
#include <cuda_fp16.h>
#include <math.h>
#include <stdint.h>

// Problem dims
#define B_  2
#define T_  2048
#define E_  1024
#define H_  16
#define D_  64
#define MROWS (B_*T_)            // 4096
#define QKVN  (3*E_)             // 3072
#define MEXP  4099               // 4E+3
// padded K dims for tensor-core GEMMs (multiples of 32)
#define KP1   1056               // pads 1025 and 1040
#define KP4   4128               // pads 4100
#define NP_ME 4224               // padded N for mlp expand (4099 -> 33*128)

// ---------------- scratch (static device globals; no allocation) -------------
__device__ __half g_l1 [MROWS*KP1];
__device__ __half g_qkv[MROWS*QKVN];
__device__ __half g_Q  [B_*H_*T_*D_];
__device__ __half g_Kr [B_*H_*T_*D_];
__device__ __half g_V  [B_*H_*T_*D_];
__device__ float  g_qt [B_*H_*T_];
__device__ float  g_kt [B_*H_*T_];
__device__ float  g_v0 [B_*H_*T_];
__device__ __half g_o  [MROWS*KP1];
__device__ float  g_y1 [MROWS*E_];
__device__ __half g_l2 [MROWS*KP1];
__device__ __half g_hp [MROWS*KP4];
__device__ float  g_hpsum[MROWS];
__device__ float  g_osum [MROWS];
// transposed + fp16-rounded + zero-padded weights: Wt[N,K]
__device__ __half g_wt_qkv[QKVN*KP1];
__device__ __half g_wt_ap [E_*KP1];
__device__ __half g_wt_me [NP_ME*KP1];
__device__ __half g_wt_ms [E_*KP4];

// ---------------- helpers -----------------------------------------------------
__device__ __forceinline__ uint32_t smem_u32(const void* p) {
    uint32_t a;
    asm("{ .reg .u64 t; cvta.to.shared.u64 t, %1; cvt.u32.u64 %0, t; }" : "=r"(a) : "l"(p));
    return a;
}
#define CP_ASYNC16(dst, src) \
    asm volatile("cp.async.cg.shared.global [%0], [%1], 16;" :: "r"(dst), "l"(src))
#define CP_COMMIT()  asm volatile("cp.async.commit_group;")
#define CP_WAIT(n)   asm volatile("cp.async.wait_group %0;" :: "n"(n))

// fp16 mma, fp32 accumulate
__device__ __forceinline__ void mma_f16(float* c, const uint32_t* a, const uint32_t* b) {
    asm volatile(
        "mma.sync.aligned.m16n8k16.row.col.f32.f16.f16.f32 "
        "{%0,%1,%2,%3}, {%4,%5,%6,%7}, {%8,%9}, {%0,%1,%2,%3};"
        : "+f"(c[0]), "+f"(c[1]), "+f"(c[2]), "+f"(c[3])
        : "r"(a[0]), "r"(a[1]), "r"(a[2]), "r"(a[3]), "r"(b[0]), "r"(b[1]));
}
__device__ __forceinline__ void ldsm_x4(uint32_t& r0, uint32_t& r1,
                                        uint32_t& r2, uint32_t& r3, uint32_t addr) {
    asm volatile("ldmatrix.sync.aligned.m8n8.x4.shared.b16 {%0,%1,%2,%3}, [%4];"
        : "=r"(r0), "=r"(r1), "=r"(r2), "=r"(r3) : "r"(addr));
}
__device__ __forceinline__ void ldsm_x4_t(uint32_t& r0, uint32_t& r1,
                                          uint32_t& r2, uint32_t& r3, uint32_t addr) {
    asm volatile("ldmatrix.sync.aligned.m8n8.x4.trans.shared.b16 {%0,%1,%2,%3}, [%4];"
        : "=r"(r0), "=r"(r1), "=r"(r2), "=r"(r3) : "r"(addr));
}

__device__ __forceinline__ float block_reduce_sum(float v, float* red) {
    int tid = threadIdx.x;
    #pragma unroll
    for (int o = 16; o; o >>= 1) v += __shfl_xor_sync(0xffffffffu, v, o);
    if ((tid & 31) == 0) red[tid >> 5] = v;
    __syncthreads();
    float r = (tid < (int)(blockDim.x >> 5)) ? red[tid] : 0.f;
    if (tid < 32) {
        #pragma unroll
        for (int o = 16; o; o >>= 1) r += __shfl_xor_sync(0xffffffffu, r, o);
        if (tid == 0) red[0] = r;
    }
    __syncthreads();
    float out = red[0];
    __syncthreads();
    return out;
}

// ---------------- merged weight transpose + fp16 round + zero pad ------------
#define TC0 (33*96)     // qkv : K=1025 N=3072 Kpad=KP1
#define TC1 (33*32)     // ap  : K=1040 N=1024 Kpad=KP1
#define TC2 (33*132)    // me  : K=1025 N=4099 Kpad=KP1, Npad=4224
#define TC3 (129*32)    // ms  : K=4100 N=1024 Kpad=KP4
__global__ void transpose_all_kernel(const float* __restrict__ w_qkv,
                                     const float* __restrict__ w_ap,
                                     const float* __restrict__ w_me,
                                     const float* __restrict__ w_ms) {
    __shared__ float s[32][33];
    int id = blockIdx.x;
    const float* W; __half* Wt;
    int K, N, Kpad, nx, r;
    if (id < TC0)                  { r = id;                W = w_qkv; Wt = g_wt_qkv; K = 1025; N = 3072; Kpad = KP1; nx = 33; }
    else if (id < TC0+TC1)         { r = id - TC0;          W = w_ap;  Wt = g_wt_ap;  K = 1040; N = 1024; Kpad = KP1; nx = 33; }
    else if (id < TC0+TC1+TC2)     { r = id - TC0 - TC1;    W = w_me;  Wt = g_wt_me;  K = 1025; N = 4099; Kpad = KP1; nx = 33; }
    else                           { r = id - TC0 - TC1-TC2;W = w_ms;  Wt = g_wt_ms;  K = 4100; N = 1024; Kpad = KP4; nx = 129; }
    int k0 = (r % nx) * 32, n0 = (r / nx) * 32;
    int tx = threadIdx.x, ty = threadIdx.y;          // 32 x 8
    #pragma unroll
    for (int yy = ty; yy < 32; yy += 8) {
        int k = k0 + yy, n = n0 + tx;
        float v = (k < K && n < N) ? W[(size_t)k * N + n] : 0.f;
        s[yy][tx] = v;
    }
    __syncthreads();
    #pragma unroll
    for (int yy = ty; yy < 32; yy += 8) {
        int n = n0 + yy, k = k0 + tx;
        Wt[(size_t)n * Kpad + k] = __float2half_rn(s[tx][yy]);
    }
}

// ---------------- fp16 tensor-core GEMM (3-stage cp.async, BK=32) -------------
// modes:
//  1: C(half)[r*ldc + 1 + c] = fp16(gelu(acc+bias)); row g^2 sums -> g_hpsum
//  2: C(half)[r*ldc + c]     = fp16(acc + bias)
//  3: C(float)[r*ldc + c]    = acc + bias + X2[r*E_ + c]
//  4: mode 3 + row sums of result^2 -> g_osum
#define HSTR 40                      // halves per SMEM row (80 B) — conflict-free
#define HBUF (128*HSTR)              // halves per buffer
#define HBYTES (HBUF*2)              // bytes per buffer (10240)
__global__ void __launch_bounds__(256, 2) gemm_f16_kernel(
        const __half* __restrict__ A, int lda,
        const __half* __restrict__ Bt, int ldb,
        const float* __restrict__ bias,
        void* __restrict__ Cv, int ldc, int Nact, int nchunks, int mode,
        const float* __restrict__ X2) {
    extern __shared__ __half hsm[];
    uint32_t smaddr = smem_u32(hsm);
    int tid = threadIdx.x;
    int lane = tid & 31, w = tid >> 5;
    int grp = lane >> 2, tig = lane & 3;
    int wm = w >> 1, wn = w & 1;
    int row0 = blockIdx.y * 128, col0 = blockIdx.x * 128;

    int q8 = lane >> 3, rr = lane & 7;
    uint32_t aoffA[2], aoffB[4];
    #pragma unroll
    for (int mi = 0; mi < 2; ++mi) {
        int rowa = wm * 32 + mi * 16 + (q8 & 1) * 8 + rr;
        aoffA[mi] = smaddr + (uint32_t)rowa * (HSTR * 2) + (q8 >> 1) * 16;
    }
    #pragma unroll
    for (int j = 0; j < 4; ++j) {
        int nb = wn * 64 + j * 16 + (q8 >> 1) * 8 + rr;
        aoffB[j] = smaddr + 3 * HBYTES + (uint32_t)nb * (HSTR * 2) + (q8 & 1) * 16;
    }

    float acc[2][8][4];
    #pragma unroll
    for (int mi = 0; mi < 2; ++mi)
        #pragma unroll
        for (int ni = 0; ni < 8; ++ni)
            #pragma unroll
            for (int cc = 0; cc < 4; ++cc) acc[mi][ni][cc] = 0.f;

    const __half* Arow = A  + (size_t)row0 * lda;
    const __half* Brow = Bt + (size_t)col0 * ldb;

    auto load_chunk = [&](int buf, int kc) {
        int k0 = kc * 32;
        uint32_t abase = smaddr + buf * HBYTES;
        uint32_t bbase = smaddr + (3 + buf) * HBYTES;
        #pragma unroll
        for (int u = 0; u < 2; ++u) {
            int idx = tid + u * 256;             // 0..511
            int r = idx >> 2, c = idx & 3;       // 128 rows x 4 16B-chunks
            CP_ASYNC16(abase + r * (HSTR * 2) + c * 16,
                       Arow + (size_t)r * lda + k0 + c * 8);
            CP_ASYNC16(bbase + r * (HSTR * 2) + c * 16,
                       Brow + (size_t)r * ldb + k0 + c * 8);
        }
        CP_COMMIT();
    };

    load_chunk(0, 0);
    load_chunk(1, 1);            // all call sites have nchunks >= 2
    int bufi = 0;
    for (int i = 0; i < nchunks; ++i) {
        if (i + 2 < nchunks) {
            int nb3 = bufi + 2; if (nb3 >= 3) nb3 -= 3;
            load_chunk(nb3, i + 2);
            CP_WAIT(2);
        }
        else if (i + 1 < nchunks) { CP_WAIT(1); }
        else { CP_WAIT(0); }
        __syncthreads();
        uint32_t bufofs = bufi * HBYTES;
        #pragma unroll
        for (int ks = 0; ks < 2; ++ks) {
            uint32_t kofs = bufofs + ks * 32;
            uint32_t a[2][4];
            ldsm_x4(a[0][0], a[0][1], a[0][2], a[0][3], aoffA[0] + kofs);
            ldsm_x4(a[1][0], a[1][1], a[1][2], a[1][3], aoffA[1] + kofs);
            uint32_t b[8][2];
            #pragma unroll
            for (int j = 0; j < 4; ++j) {
                uint32_t r0, r1, r2, r3;
                ldsm_x4(r0, r1, r2, r3, aoffB[j] + kofs);
                b[2*j][0] = r0;   b[2*j][1] = r1;
                b[2*j+1][0] = r2; b[2*j+1][1] = r3;
            }
            #pragma unroll
            for (int mi = 0; mi < 2; ++mi)
                #pragma unroll
                for (int ni = 0; ni < 8; ++ni)
                    mma_f16(acc[mi][ni], a[mi], b[ni]);
        }
        __syncthreads();
        bufi = (bufi == 2) ? 0 : bufi + 1;
    }

    if (mode == 2) {
        __half* C = (__half*)Cv;
        #pragma unroll
        for (int mi = 0; mi < 2; ++mi) {
            int rbase = row0 + wm * 32 + mi * 16 + grp;
            #pragma unroll
            for (int ni = 0; ni < 8; ++ni) {
                int gc = col0 + wn * 64 + ni * 8 + tig * 2;
                if (gc < Nact) {
                    float b0 = bias ? bias[gc] : 0.f;
                    float b1 = (bias && gc + 1 < Nact) ? bias[gc + 1] : 0.f;
                    __half* p0 = C + (size_t)rbase * ldc + gc;
                    __half* p1 = C + (size_t)(rbase + 8) * ldc + gc;
                    p0[0] = __float2half_rn(acc[mi][ni][0] + b0);
                    if (gc + 1 < Nact) p0[1] = __float2half_rn(acc[mi][ni][1] + b1);
                    p1[0] = __float2half_rn(acc[mi][ni][2] + b0);
                    if (gc + 1 < Nact) p1[1] = __float2half_rn(acc[mi][ni][3] + b1);
                }
            }
        }
    } else if (mode == 1) {
        __half* C = (__half*)Cv;
        float rsum[2][2] = {{0.f, 0.f}, {0.f, 0.f}};
        #pragma unroll
        for (int mi = 0; mi < 2; ++mi) {
            int rbase = row0 + wm * 32 + mi * 16 + grp;
            #pragma unroll
            for (int ni = 0; ni < 8; ++ni) {
                int gc = col0 + wn * 64 + ni * 8 + tig * 2;
                if (gc < Nact) {
                    float b0 = bias ? bias[gc] : 0.f;
                    float b1 = (bias && gc + 1 < Nact) ? bias[gc + 1] : 0.f;
                    float v0 = acc[mi][ni][0] + b0;
                    float v1 = acc[mi][ni][1] + b1;
                    float v2 = acc[mi][ni][2] + b0;
                    float v3 = acc[mi][ni][3] + b1;
                    float g0 = 0.5f * v0 * (1.0f + erff(v0 * 0.70710678118654752f));
                    float g1 = 0.5f * v1 * (1.0f + erff(v1 * 0.70710678118654752f));
                    float g2 = 0.5f * v2 * (1.0f + erff(v2 * 0.70710678118654752f));
                    float g3 = 0.5f * v3 * (1.0f + erff(v3 * 0.70710678118654752f));
                    __half* p0 = C + (size_t)rbase * ldc + 1 + gc;
                    __half* p1 = C + (size_t)(rbase + 8) * ldc + 1 + gc;
                    p0[0] = __float2half_rn(g0);
                    rsum[mi][0] += g0 * g0;
                    rsum[mi][1] += g2 * g2;
                    if (gc + 1 < Nact) {
                        p0[1] = __float2half_rn(g1);
                        rsum[mi][0] += g1 * g1;
                        rsum[mi][1] += g3 * g3;
                    }
                    p1[0] = __float2half_rn(g2);
                    if (gc + 1 < Nact) p1[1] = __float2half_rn(g3);
                }
            }
        }
        #pragma unroll
        for (int m = 1; m < 4; m <<= 1) {
            rsum[0][0] += __shfl_xor_sync(0xffffffffu, rsum[0][0], m);
            rsum[0][1] += __shfl_xor_sync(0xffffffffu, rsum[0][1], m);
            rsum[1][0] += __shfl_xor_sync(0xffffffffu, rsum[1][0], m);
            rsum[1][1] += __shfl_xor_sync(0xffffffffu, rsum[1][1], m);
        }
        if (tig == 0) {
            #pragma unroll
            for (int mi = 0; mi < 2; ++mi) {
                int rbase = row0 + wm * 32 + mi * 16 + grp;
                atomicAdd(&g_hpsum[rbase], rsum[mi][0]);
                atomicAdd(&g_hpsum[rbase + 8], rsum[mi][1]);
            }
        }
    } else {   // modes 3/4: fp32 out with fused residual add (X2 stride E_)
        float* C = (float*)Cv;
        float rsum[2][2] = {{0.f, 0.f}, {0.f, 0.f}};
        #pragma unroll
        for (int mi = 0; mi < 2; ++mi) {
            int rbase = row0 + wm * 32 + mi * 16 + grp;
            #pragma unroll
            for (int ni = 0; ni < 8; ++ni) {
                int gc = col0 + wn * 64 + ni * 8 + tig * 2;
                if (gc < Nact) {
                    float b0 = bias ? bias[gc] : 0.f;
                    float b1 = (bias && gc + 1 < Nact) ? bias[gc + 1] : 0.f;
                    const float* x0 = X2 + (size_t)rbase * E_ + gc;
                    const float* x1 = X2 + (size_t)(rbase + 8) * E_ + gc;
                    float* p0 = C + (size_t)rbase * ldc + gc;
                    float* p1 = C + (size_t)(rbase + 8) * ldc + gc;
                    float y0 = acc[mi][ni][0] + b0 + x0[0];
                    float y2 = acc[mi][ni][2] + b0 + x1[0];
                    p0[0] = y0;
                    p1[0] = y2;
                    rsum[mi][0] += y0 * y0;
                    rsum[mi][1] += y2 * y2;
                    if (gc + 1 < Nact) {
                        float y1v = acc[mi][ni][1] + b1 + x0[1];
                        float y3v = acc[mi][ni][3] + b1 + x1[1];
                        p0[1] = y1v;
                        p1[1] = y3v;
                        rsum[mi][0] += y1v * y1v;
                        rsum[mi][1] += y3v * y3v;
                    }
                }
            }
        }
        if (mode == 4) {
            #pragma unroll
            for (int m = 1; m < 4; m <<= 1) {
                rsum[0][0] += __shfl_xor_sync(0xffffffffu, rsum[0][0], m);
                rsum[0][1] += __shfl_xor_sync(0xffffffffu, rsum[0][1], m);
                rsum[1][0] += __shfl_xor_sync(0xffffffffu, rsum[1][0], m);
                rsum[1][1] += __shfl_xor_sync(0xffffffffu, rsum[1][1], m);
            }
            if (tig == 0) {
                #pragma unroll
                for (int mi = 0; mi < 2; ++mi) {
                    int rbase = row0 + wm * 32 + mi * 16 + grp;
                    atomicAdd(&g_osum[rbase], rsum[mi][0]);
                    atomicAdd(&g_osum[rbase + 8], rsum[mi][1]);
                }
            }
        }
    }
}

// ---------------- kernel 1: LN + project of x -> l1 (M, KP1) half -------------
__global__ void ln_project_kernel(const float* __restrict__ x,
                                  const float* __restrict__ lnw,
                                  const float* __restrict__ lnb,
                                  const float* __restrict__ bc,
                                  __half* __restrict__ out) {
    int row = blockIdx.x;
    int tid = threadIdx.x;
    const float* xr = x + (size_t)row * E_;
    __shared__ float red[32];
    float loc[4];
    float s = 0.f;
    #pragma unroll
    for (int u = 0; u < 4; ++u) { loc[u] = xr[tid + u * 256]; s += loc[u]; }
    float mean = block_reduce_sum(s, red) * (1.0f / E_);
    float vs = 0.f;
    #pragma unroll
    for (int u = 0; u < 4; ++u) { float d = loc[u] - mean; vs += d * d; }
    float var = block_reduce_sum(vs, red) * (1.0f / E_);
    float rstd = rsqrtf(var + 1e-5f);
    float Kb = expf(bc[0]);
    float ss = 0.f;
    __half* orow = out + (size_t)row * KP1;
    #pragma unroll
    for (int u = 0; u < 4; ++u) {
        int c = tid + u * 256;
        float y = (loc[u] - mean) * rstd * lnw[c] + lnb[c];
        orow[1 + c] = __float2half_rn(y);
        ss += y * y;
    }
    float sst = block_reduce_sum(ss, red);
    if (tid == 0) orow[0] = __float2half_rn(sqrtf(Kb + sst));
    if (tid < 31) orow[1025 + tid] = __float2half_rn(0.f);
}

// ---------------- kernel 3: RoPE + per-head norms (fp16 Q/K/V) ---------------
__global__ void rope_prep_kernel(const float* __restrict__ curv) {
    int tid = threadIdx.x;
    int lane = tid & 31;
    int rsub = tid >> 5;
    int r = blockIdx.x * 8 + rsub;            // r = bh*T + t
    int bh = r >> 11;
    int t  = r & (T_ - 1);
    int b  = bh >> 4;
    int h  = bh & 15;
    float Ka = expf(curv[h]);
    size_t base = ((size_t)(b * T_ + t)) * QKVN + h * D_;
    float q1 = __half2float(g_qkv[base + lane]);
    float q2 = __half2float(g_qkv[base + 32 + lane]);
    float k1 = __half2float(g_qkv[base + E_ + lane]);
    float k2 = __half2float(g_qkv[base + E_ + 32 + lane]);
    float v1 = __half2float(g_qkv[base + 2*E_ + lane]);
    float v2 = __half2float(g_qkv[base + 2*E_ + 32 + lane]);
    float inv = powf(10000.0f, -(float)lane * (1.0f / 32.0f));
    float fr = (float)t * inv;
    float sn, cs;
    sincosf(fr, &sn, &cs);
    __half qah = __float2half_rn(q1 * cs + q2 * sn);
    __half qbh = __float2half_rn(-q1 * sn + q2 * cs);
    __half kah = __float2half_rn(k1 * cs + k2 * sn);
    __half kbh = __float2half_rn(-k1 * sn + k2 * cs);
    float qa = __half2float(qah), qb = __half2float(qbh);
    float ka = __half2float(kah), kb = __half2float(kbh);
    float sq = qa * qa + qb * qb;
    float sk = ka * ka + kb * kb;
    float sv = v1 * v1 + v2 * v2;
    #pragma unroll
    for (int o = 16; o; o >>= 1) {
        sq += __shfl_xor_sync(0xffffffffu, sq, o);
        sk += __shfl_xor_sync(0xffffffffu, sk, o);
        sv += __shfl_xor_sync(0xffffffffu, sv, o);
    }
    size_t ob = ((size_t)bh * T_ + t) * D_;
    g_Q[ob + lane] = qah;  g_Q[ob + 32 + lane] = qbh;
    g_Kr[ob + lane] = kah; g_Kr[ob + 32 + lane] = kbh;
    g_V[ob + lane] = __float2half_rn(v1);
    g_V[ob + 32 + lane] = __float2half_rn(v2);
    if (lane == 0) {
        g_qt[r] = sqrtf(Ka + sq);
        g_kt[r] = sqrtf(Ka + sk);
        g_v0[r] = sqrtf(Ka + sv);
    }
}

// ---------------- kernel 4: hyperbolic causal attention (all-fp16 mma) -------
// cp.async double-buffered K/V/kt/v0 tiles; longest q-tiles launched first.
#define KVSTR 72                 // halves per K/V smem row (144 B, D=64 + pad)
#define KVBYTES (32*KVSTR*2)     // 4608 B per tile buffer
#define PSCALE 1024.0f
#define RPSCALE (1.0f/1024.0f)
__global__ void __launch_bounds__(256, 2) attn_kernel(const float* __restrict__ curv) {
    __shared__ __align__(16) __half ksh[2 * 32 * KVSTR];
    __shared__ __align__(16) __half vsh[2 * 32 * KVSTR];
    __shared__ __align__(16) float kts[2 * 32];
    __shared__ __align__(16) float v0s[2 * 32];

    int bh = blockIdx.y;
    int b = bh >> 4, h = bh & 15;
    int q0 = ((int)gridDim.x - 1 - (int)blockIdx.x) * 128;   // longest first
    int tid = threadIdx.x, lane = tid & 31, w = tid >> 5;
    int grp = lane >> 2, tig = lane & 3;
    float Ka = expf(curv[h]);
    float sK = sqrtf(Ka);
    float rKa = 1.0f / Ka;
    float nsK = -sK;

    int r0 = q0 + w * 16 + grp;
    int r1 = r0 + 8;

    uint32_t kshaddr = smem_u32(ksh);
    uint32_t vshaddr = smem_u32(vsh);
    uint32_t ktsaddr = smem_u32(kts);
    uint32_t v0saddr = smem_u32(v0s);
    int q8 = lane >> 3, rr = lane & 7;
    uint32_t aoffK[2];
    #pragma unroll
    for (int j = 0; j < 2; ++j) {
        int nb = j * 16 + (q8 >> 1) * 8 + rr;
        aoffK[j] = kshaddr + (uint32_t)nb * (KVSTR * 2) + (q8 & 1) * 16;
    }
    uint32_t aoffV[4];
    {
        int krow = (q8 & 1) * 8 + rr;
        int ncol = (q8 >> 1) * 8;
        #pragma unroll
        for (int j = 0; j < 4; ++j)
            aoffV[j] = vshaddr + (uint32_t)(krow * KVSTR + j * 16 + ncol) * 2;
    }

    uint32_t qh[4][4];
    {
        const __half* Q0 = g_Q + ((size_t)bh * T_ + r0) * D_;
        const __half* Q1 = g_Q + ((size_t)bh * T_ + r1) * D_;
        #pragma unroll
        for (int ks = 0; ks < 4; ++ks) {
            qh[ks][0] = *(const uint32_t*)(Q0 + ks * 16 + 2 * tig);
            qh[ks][1] = *(const uint32_t*)(Q1 + ks * 16 + 2 * tig);
            qh[ks][2] = *(const uint32_t*)(Q0 + ks * 16 + 8 + 2 * tig);
            qh[ks][3] = *(const uint32_t*)(Q1 + ks * 16 + 8 + 2 * tig);
        }
    }
    float qt0 = g_qt[(size_t)bh * T_ + r0];
    float qt1 = g_qt[(size_t)bh * T_ + r1];

    float oacc[8][4];
    #pragma unroll
    for (int nb = 0; nb < 8; ++nb)
        #pragma unroll
        for (int cc = 0; cc < 4; ++cc) oacc[nb][cc] = 0.f;
    float ssum0 = 0.f, ssum1 = 0.f, o00 = 0.f, o01 = 0.f;

    // cp.async prefetch of one K/V chunk into buffer `buf`
    auto prefetch = [&](int buf, int k0c) {
        int rr2 = tid >> 3, c = tid & 7;
        CP_ASYNC16(kshaddr + buf * KVBYTES + rr2 * (KVSTR * 2) + c * 16,
                   g_Kr + ((size_t)bh * T_ + k0c + rr2) * D_ + c * 8);
        CP_ASYNC16(vshaddr + buf * KVBYTES + rr2 * (KVSTR * 2) + c * 16,
                   g_V + ((size_t)bh * T_ + k0c + rr2) * D_ + c * 8);
        if (tid < 8)
            CP_ASYNC16(ktsaddr + buf * 128 + tid * 16,
                       g_kt + (size_t)bh * T_ + k0c + tid * 4);
        else if (tid < 16)
            CP_ASYNC16(v0saddr + buf * 128 + (tid - 8) * 16,
                       g_v0 + (size_t)bh * T_ + k0c + (tid - 8) * 4);
        CP_COMMIT();
    };

    int nch = q0 / 32 + 4;
    prefetch(0, 0);
    for (int i = 0; i < nch; ++i) {
        int k0 = i * 32;
        int buf = i & 1;
        __syncthreads();               // prior compute done (buffer reuse safe)
        if (i + 1 < nch) { prefetch(buf ^ 1, k0 + 32); CP_WAIT(1); }
        else             { CP_WAIT(0); }
        __syncthreads();               // chunk i visible to all threads
        if (q0 + w * 16 + 15 < k0) continue;

        uint32_t bufK = buf * KVBYTES;
        int bufS = buf * 32;

        float sacc[4][4];
        #pragma unroll
        for (int nb = 0; nb < 4; ++nb)
            #pragma unroll
            for (int cc = 0; cc < 4; ++cc) sacc[nb][cc] = 0.f;
        #pragma unroll
        for (int ks = 0; ks < 4; ++ks) {
            uint32_t kofs = bufK + ks * 32;
            uint32_t bb[4][2];
            #pragma unroll
            for (int j = 0; j < 2; ++j) {
                uint32_t f0, f1, f2, f3;
                ldsm_x4(f0, f1, f2, f3, aoffK[j] + kofs);
                bb[2*j][0] = f0;   bb[2*j][1] = f1;
                bb[2*j+1][0] = f2; bb[2*j+1][1] = f3;
            }
            #pragma unroll
            for (int nb = 0; nb < 4; ++nb)
                mma_f16(sacc[nb], qh[ks], bb[nb]);
        }

        uint32_t ap[4][2];
        #pragma unroll
        for (int nb = 0; nb < 4; ++nb) {
            int cl = nb * 8 + 2 * tig;
            float ktc0 = kts[bufS + cl], ktc1 = kts[bufS + cl + 1];
            float v0c0 = v0s[bufS + cl], v0c1 = v0s[bufS + cl + 1];
            int cg0 = k0 + cl, cg1 = cg0 + 1;
            float p0, p1, p2, p3;
            {
                float ratio = fmaxf(-(sacc[nb][0] - qt0 * ktc0) * rKa, 1.0f + 1e-7f);
                float arg = ratio + sqrtf((ratio - 1.f) * (ratio + 1.f));
                p0 = (cg0 <= r0) ? __expf(nsK * __logf(arg)) : 0.f;
            }
            {
                float ratio = fmaxf(-(sacc[nb][1] - qt0 * ktc1) * rKa, 1.0f + 1e-7f);
                float arg = ratio + sqrtf((ratio - 1.f) * (ratio + 1.f));
                p1 = (cg1 <= r0) ? __expf(nsK * __logf(arg)) : 0.f;
            }
            {
                float ratio = fmaxf(-(sacc[nb][2] - qt1 * ktc0) * rKa, 1.0f + 1e-7f);
                float arg = ratio + sqrtf((ratio - 1.f) * (ratio + 1.f));
                p2 = (cg0 <= r1) ? __expf(nsK * __logf(arg)) : 0.f;
            }
            {
                float ratio = fmaxf(-(sacc[nb][3] - qt1 * ktc1) * rKa, 1.0f + 1e-7f);
                float arg = ratio + sqrtf((ratio - 1.f) * (ratio + 1.f));
                p3 = (cg1 <= r1) ? __expf(nsK * __logf(arg)) : 0.f;
            }
            ssum0 += p0 + p1;  o00 += p0 * v0c0 + p1 * v0c1;
            ssum1 += p2 + p3;  o01 += p2 * v0c0 + p3 * v0c1;
            __half2 h01 = __floats2half2_rn(p0 * PSCALE, p1 * PSCALE);
            __half2 h23 = __floats2half2_rn(p2 * PSCALE, p3 * PSCALE);
            ap[nb][0] = *(uint32_t*)&h01;
            ap[nb][1] = *(uint32_t*)&h23;
        }

        #pragma unroll
        for (int ks = 0; ks < 2; ++ks) {
            uint32_t A[4] = { ap[2*ks][0], ap[2*ks][1], ap[2*ks+1][0], ap[2*ks+1][1] };
            uint32_t vofs = bufK + ks * (16 * KVSTR * 2);
            #pragma unroll
            for (int j = 0; j < 4; ++j) {
                uint32_t f0, f1, f2, f3;
                ldsm_x4_t(f0, f1, f2, f3, aoffV[j] + vofs);
                uint32_t B0[2] = { f0, f1 };
                uint32_t B1[2] = { f2, f3 };
                mma_f16(oacc[2*j],     A, B0);
                mma_f16(oacc[2*j + 1], A, B1);
            }
        }
    }

    #pragma unroll
    for (int m = 1; m < 4; m <<= 1) {
        ssum0 += __shfl_xor_sync(0xffffffffu, ssum0, m);
        ssum1 += __shfl_xor_sync(0xffffffffu, ssum1, m);
        o00   += __shfl_xor_sync(0xffffffffu, o00, m);
        o01   += __shfl_xor_sync(0xffffffffu, o01, m);
    }
    float rs0 = 1.0f / ssum0, rs1 = 1.0f / ssum1;
    float on0 = o00 * rs0, on1 = o01 * rs1;
    float rso0 = rs0 * RPSCALE, rso1 = rs1 * RPSCALE;
    float s20 = 0.f, s21 = 0.f;
    #pragma unroll
    for (int nb = 0; nb < 8; ++nb) {
        float a0 = oacc[nb][0] * rso0, a1 = oacc[nb][1] * rso0;
        float a2 = oacc[nb][2] * rso1, a3 = oacc[nb][3] * rso1;
        oacc[nb][0] = a0; oacc[nb][1] = a1; oacc[nb][2] = a2; oacc[nb][3] = a3;
        s20 += a0 * a0 + a1 * a1;
        s21 += a2 * a2 + a3 * a3;
    }
    #pragma unroll
    for (int m = 1; m < 4; m <<= 1) {
        s20 += __shfl_xor_sync(0xffffffffu, s20, m);
        s21 += __shfl_xor_sync(0xffffffffu, s21, m);
    }
    float hn0 = sqrtf(fmaxf(on0 * on0 - s20, 1e-12f));
    float hn1 = sqrtf(fmaxf(on1 * on1 - s21, 1e-12f));
    float sc0 = sK / hn0, sc1 = sK / hn1;

    __half* base0 = g_o + ((size_t)(b * T_ + r0)) * KP1 + h * 65;
    __half* base1 = g_o + ((size_t)(b * T_ + r1)) * KP1 + h * 65;
    if (tig == 0) {
        base0[0] = __float2half_rn(on0 * sc0);
        base1[0] = __float2half_rn(on1 * sc1);
    }
    #pragma unroll
    for (int nb = 0; nb < 8; ++nb) {
        int c = nb * 8 + 2 * tig;
        base0[1 + c]     = __float2half_rn(oacc[nb][0] * sc0);
        base0[1 + c + 1] = __float2half_rn(oacc[nb][1] * sc0);
        base1[1 + c]     = __float2half_rn(oacc[nb][2] * sc1);
        base1[1 + c + 1] = __float2half_rn(oacc[nb][3] * sc1);
    }
    if (h == 15) {
        __half* pr0 = g_o + ((size_t)(b * T_ + r0)) * KP1;
        __half* pr1 = g_o + ((size_t)(b * T_ + r1)) * KP1;
        #pragma unroll
        for (int i = 0; i < 4; ++i) {
            pr0[1040 + tig * 4 + i] = __float2half_rn(0.f);
            pr1[1040 + tig * 4 + i] = __float2half_rn(0.f);
        }
    }
}

// ---------------- kernel 6: LN + project of y1 -> l2 (also zeroes g_hpsum) ---
__global__ void resid_ln_project_kernel(const float* __restrict__ lnw,
                                        const float* __restrict__ lnb,
                                        const float* __restrict__ bc) {
    int row = blockIdx.x;
    int tid = threadIdx.x;
    const float* yr = g_y1 + (size_t)row * E_;
    __shared__ float red[32];
    float loc[4];
    float s = 0.f;
    #pragma unroll
    for (int u = 0; u < 4; ++u) {
        loc[u] = yr[tid + u * 256];
        s += loc[u];
    }
    float mean = block_reduce_sum(s, red) * (1.0f / E_);
    float vs = 0.f;
    #pragma unroll
    for (int u = 0; u < 4; ++u) { float d = loc[u] - mean; vs += d * d; }
    float var = block_reduce_sum(vs, red) * (1.0f / E_);
    float rstd = rsqrtf(var + 1e-5f);
    float Kb = expf(bc[0]);
    float ss = 0.f;
    __half* orow = g_l2 + (size_t)row * KP1;
    #pragma unroll
    for (int u = 0; u < 4; ++u) {
        int c = tid + u * 256;
        float y = (loc[u] - mean) * rstd * lnw[c] + lnb[c];
        orow[1 + c] = __float2half_rn(y);
        ss += y * y;
    }
    float sst = block_reduce_sum(ss, red);
    if (tid == 0) {
        orow[0] = __float2half_rn(sqrtf(Kb + sst));
        g_hpsum[row] = 0.f;
    }
    if (tid < 31) orow[1025 + tid] = __float2half_rn(0.f);
}

// ---------------- kernel 8: hp norm finalize (+ zero g_osum, pad) ------------
__global__ void hp_finalize_kernel(const float* __restrict__ mc) {
    int row = blockIdx.x;
    int tid = threadIdx.x;        // 32 threads
    __half* op = g_hp + (size_t)row * KP4;
    if (tid == 0) {
        op[0] = __float2half_rn(sqrtf(expf(mc[0]) + g_hpsum[row]));
        g_osum[row] = 0.f;
    }
    if (tid < 28) op[4100 + tid] = __float2half_rn(0.f);
}

// ---------------- kernel 10: final norm column from fused sums ----------------
__global__ void final_finalize_kernel(const float* __restrict__ bc,
                                      float* __restrict__ out) {
    int idx = blockIdx.x * 256 + threadIdx.x;
    float Kb = expf(bc[0]);
    out[(size_t)idx * (E_ + 1)] = sqrtf(Kb + g_osum[idx]);
}

// ---------------- launch -----------------------------------------------------
extern "C" void kernel_launch(void* const* d_in, const int* in_sizes, int n_in,
                              void* d_out, int out_size) {
    const float* x      = (const float*)d_in[0];
    const float* bc     = (const float*)d_in[1];
    const float* mc     = (const float*)d_in[2];
    const float* acurv  = (const float*)d_in[3];
    const float* w_qkv  = (const float*)d_in[4];
    const float* w_ap   = (const float*)d_in[5];
    const float* b_ap   = (const float*)d_in[6];
    const float* w_me   = (const float*)d_in[7];
    const float* b_me   = (const float*)d_in[8];
    const float* w_ms   = (const float*)d_in[9];
    const float* b_ms   = (const float*)d_in[10];
    const float* lnw    = (const float*)d_in[11];
    const float* lnb    = (const float*)d_in[12];
    float* out = (float*)d_out;

    __half *p_l1, *p_qkv, *p_o, *p_l2, *p_hp, *p_wq, *p_wa, *p_we, *p_ws;
    float  *p_y1;
    cudaGetSymbolAddress((void**)&p_l1,  g_l1);
    cudaGetSymbolAddress((void**)&p_qkv, g_qkv);
    cudaGetSymbolAddress((void**)&p_o,   g_o);
    cudaGetSymbolAddress((void**)&p_y1,  g_y1);
    cudaGetSymbolAddress((void**)&p_l2,  g_l2);
    cudaGetSymbolAddress((void**)&p_hp,  g_hp);
    cudaGetSymbolAddress((void**)&p_wq,  g_wt_qkv);
    cudaGetSymbolAddress((void**)&p_wa,  g_wt_ap);
    cudaGetSymbolAddress((void**)&p_we,  g_wt_me);
    cudaGetSymbolAddress((void**)&p_ws,  g_wt_ms);

    const int GSMEM = 6 * HBYTES;   // 61440 bytes (3-stage A + 3-stage B)
    cudaFuncSetAttribute(gemm_f16_kernel,
                         cudaFuncAttributeMaxDynamicSharedMemorySize, GSMEM);

    transpose_all_kernel<<<TC0 + TC1 + TC2 + TC3, dim3(32, 8)>>>(
        w_qkv, w_ap, w_me, w_ms);

    ln_project_kernel<<<MROWS, 256>>>(x, lnw, lnb, bc, p_l1);
    // qkv = l1 @ Wqkv (half out)
    gemm_f16_kernel<<<dim3(QKVN/128, MROWS/128), 256, GSMEM>>>(
        p_l1, KP1, p_wq, KP1, nullptr, p_qkv, QKVN, QKVN, KP1/32, 2, nullptr);
    rope_prep_kernel<<<(B_ * H_ * T_) / 8, 256>>>(acurv);
    attn_kernel<<<dim3(T_ / 128, B_ * H_), 256>>>(acurv);
    // y1 = o @ Wap + b_ap + x  (fp32, fused residual)
    gemm_f16_kernel<<<dim3(E_/128, MROWS/128), 256, GSMEM>>>(
        p_o, KP1, p_wa, KP1, b_ap, p_y1, E_, E_, KP1/32, 3, x);
    resid_ln_project_kernel<<<MROWS, 256>>>(lnw, lnb, bc);
    // hp[.,1+c] = gelu(l2 @ Wme + b_me); row sums -> g_hpsum
    gemm_f16_kernel<<<dim3(NP_ME/128, MROWS/128), 256, GSMEM>>>(
        p_l2, KP1, p_we, KP1, b_me, p_hp, KP4, MEXP, KP1/32, 1, nullptr);
    hp_finalize_kernel<<<MROWS, 32>>>(mc);
    // out[.,1+c] = hp @ Wms + b_ms + y1; row sums -> g_osum
    gemm_f16_kernel<<<dim3(E_/128, MROWS/128), 256, GSMEM>>>(
        p_hp, KP4, p_ws, KP4, b_ms, out + 1, E_ + 1, E_, KP4/32, 4, p_y1);
    final_finalize_kernel<<<MROWS/256, 256>>>(bc, out);
}